// round 11
// baseline (speedup 1.0000x reference)
#include <cuda_runtime.h>
#include <cuda_bf16.h>
#include <cuda_fp16.h>
#include <cstdint>

#define N_SNP  100000
#define N_GENE 20000
#define N_ALL  120000
#define HID    128
#define NEG    0.2f

#define E_SG_MAX 500000
#define E_GS_MAX 500000
#define E_GG_MAX 150000

#define SEG_GS 20000
#define SEG_GG 120000
#define NSEG_TOT 140000
#define NB_SG 20
#define NB_GS 98
#define NB_GG 20
#define NB_TOT 138

#define TG_BLKS 157

#define WROW   272
#define WLO    34816
#define WIMGSZ 69632

// ---------------- device scratch ----------------
__device__ __half   g_hsh[N_SNP * HID];
__device__ __half   g_hgh[N_GENE * HID];
__device__ float    g_ssrc_sg[N_SNP * 8];
__device__ float    g_sdst_gs[N_SNP * 8];
__device__ float    g_sdst_sg[N_GENE * 8];
__device__ float    g_ssrc_gs[N_GENE * 8];
__device__ float    g_ssrc_gg[N_GENE * 8];
__device__ float    g_sdst_gg[N_GENE * 8];
__device__ float    g_o_sg[N_GENE * HID];
__device__ float    g_o_gg[N_GENE * HID];
__device__ float    g_out_s0[N_SNP * HID];
__device__ float    g_out_g0[N_GENE * HID];
__device__ float    g_sempart[2 * TG_BLKS * HID];
__device__ float    g_buf1[N_ALL * HID];
__device__ __align__(16) unsigned char g_wimg[8 * WIMGSZ];
__device__ int g_rp_sg[N_GENE + 1];
__device__ int g_rp_gs[N_SNP + 1];
__device__ int g_rp_gg[N_GENE + 1];
__device__ int g_dc[2 * NSEG_TOT];
__device__ int g_bsum[NB_TOT + 4];
__device__ int g_ss_sg[E_SG_MAX];
__device__ int g_ss_gs[E_GS_MAX];
__device__ int g_ss_gg[E_GG_MAX];

__device__ __forceinline__ uint32_t pack_bf(float x, float y) {
    __nv_bfloat162 t = __floats2bfloat162_rn(x, y);
    return *(uint32_t*)&t;
}
__device__ __forceinline__ void mma_bf16(float4& c, uint32_t a0, uint32_t a1,
                                         uint32_t a2, uint32_t a3,
                                         uint32_t b0, uint32_t b1) {
    asm volatile("mma.sync.aligned.m16n8k16.row.col.f32.bf16.bf16.f32 "
                 "{%0,%1,%2,%3}, {%4,%5,%6,%7}, {%8,%9}, {%0,%1,%2,%3};"
                 : "+f"(c.x), "+f"(c.y), "+f"(c.z), "+f"(c.w)
                 : "r"(a0), "r"(a1), "r"(a2), "r"(a3), "r"(b0), "r"(b1));
}

// Core GEMM: 16-row strip pair per warp from gmem fp32 A vs smem weight image.
__device__ __forceinline__ void gemm_core(
    const float* __restrict__ A, int rowA, int rowB, bool vA, bool vB,
    const unsigned char* sm, int lane, float4 acc[16])
{
    const int g = lane >> 2, tig = lane & 3;
    const float* ArA = A + (size_t)rowA * 128;
    const float* ArB = A + (size_t)rowB * 128;
#pragma unroll
    for (int ks = 0; ks < 8; ks++) {
        const int k0 = ks * 16;
        float2 p00 = make_float2(0.f, 0.f), p01 = p00, p10 = p00, p11 = p00;
        if (vA) {
            p00 = *(const float2*)(ArA + k0 + 2 * tig);
            p01 = *(const float2*)(ArA + k0 + 2 * tig + 8);
        }
        if (vB) {
            p10 = *(const float2*)(ArB + k0 + 2 * tig);
            p11 = *(const float2*)(ArB + k0 + 2 * tig + 8);
        }
        uint32_t ah0 = pack_bf(p00.x, p00.y), ah1 = pack_bf(p10.x, p10.y);
        uint32_t ah2 = pack_bf(p01.x, p01.y), ah3 = pack_bf(p11.x, p11.y);
        __nv_bfloat162 h00 = *(__nv_bfloat162*)&ah0, h10 = *(__nv_bfloat162*)&ah1;
        __nv_bfloat162 h01 = *(__nv_bfloat162*)&ah2, h11 = *(__nv_bfloat162*)&ah3;
        uint32_t al0 = pack_bf(p00.x - __bfloat162float(h00.x), p00.y - __bfloat162float(h00.y));
        uint32_t al1 = pack_bf(p10.x - __bfloat162float(h10.x), p10.y - __bfloat162float(h10.y));
        uint32_t al2 = pack_bf(p01.x - __bfloat162float(h01.x), p01.y - __bfloat162float(h01.y));
        uint32_t al3 = pack_bf(p11.x - __bfloat162float(h11.x), p11.y - __bfloat162float(h11.y));

        const unsigned char* bh = sm + (size_t)g * WROW + (k0 + 2 * tig) * 2;
#pragma unroll
        for (int nt = 0; nt < 16; nt++) {
            uint32_t bh0 = *(const uint32_t*)(bh + nt * 8 * WROW);
            uint32_t bh1 = *(const uint32_t*)(bh + nt * 8 * WROW + 16);
            mma_bf16(acc[nt], ah0, ah1, ah2, ah3, bh0, bh1);
            mma_bf16(acc[nt], al0, al1, al2, al3, bh0, bh1);
            uint32_t bl0 = *(const uint32_t*)(bh + WLO + nt * 8 * WROW);
            uint32_t bl1 = *(const uint32_t*)(bh + WLO + nt * 8 * WROW + 16);
            mma_bf16(acc[nt], ah0, ah1, ah2, ah3, bl0, bl1);
        }
    }
}

// Second GEMM with A operand coming from register accumulators.
__device__ __forceinline__ void gemm_core_reg(
    const float4 a1[16], const unsigned char* sm, int lane, float4 acc[16])
{
    const int g = lane >> 2, tig = lane & 3;
#pragma unroll
    for (int kt = 0; kt < 8; kt++) {
        float x0 = a1[2*kt].x,   y0 = a1[2*kt].y;
        float x1 = a1[2*kt].z,   y1 = a1[2*kt].w;
        float x2 = a1[2*kt+1].x, y2 = a1[2*kt+1].y;
        float x3 = a1[2*kt+1].z, y3 = a1[2*kt+1].w;
        uint32_t ah0 = pack_bf(x0, y0), ah1 = pack_bf(x1, y1);
        uint32_t ah2 = pack_bf(x2, y2), ah3 = pack_bf(x3, y3);
        __nv_bfloat162 h0 = *(__nv_bfloat162*)&ah0, h1 = *(__nv_bfloat162*)&ah1;
        __nv_bfloat162 h2 = *(__nv_bfloat162*)&ah2, h3 = *(__nv_bfloat162*)&ah3;
        uint32_t al0 = pack_bf(x0 - __bfloat162float(h0.x), y0 - __bfloat162float(h0.y));
        uint32_t al1 = pack_bf(x1 - __bfloat162float(h1.x), y1 - __bfloat162float(h1.y));
        uint32_t al2 = pack_bf(x2 - __bfloat162float(h2.x), y2 - __bfloat162float(h2.y));
        uint32_t al3 = pack_bf(x3 - __bfloat162float(h3.x), y3 - __bfloat162float(h3.y));

        const unsigned char* bh = sm + (size_t)g * WROW + (kt * 16 + 2 * tig) * 2;
#pragma unroll
        for (int nt = 0; nt < 16; nt++) {
            uint32_t bh0 = *(const uint32_t*)(bh + nt * 8 * WROW);
            uint32_t bh1 = *(const uint32_t*)(bh + nt * 8 * WROW + 16);
            mma_bf16(acc[nt], ah0, ah1, ah2, ah3, bh0, bh1);
            mma_bf16(acc[nt], al0, al1, al2, al3, bh0, bh1);
            uint32_t bl0 = *(const uint32_t*)(bh + WLO + nt * 8 * WROW);
            uint32_t bl1 = *(const uint32_t*)(bh + WLO + nt * 8 * WROW + 16);
            mma_bf16(acc[nt], ah0, ah1, ah2, ah3, bl0, bl1);
        }
    }
}

// ---------------- prep: zero counters + weight images in ONE launch ----------------
#define ZB 1094   // cdiv(2*NSEG_TOT,256)
__global__ void prep_k(const float* __restrict__ W0, const float* __restrict__ W1,
                       const float* __restrict__ W2, const float* __restrict__ W3,
                       const float* __restrict__ W4, const float* __restrict__ W5,
                       const float* __restrict__ W6, const float* __restrict__ W7,
                       unsigned char* __restrict__ imgbase) {
    if (blockIdx.x < ZB) {
        int i = blockIdx.x * 256 + threadIdx.x;
        if (i < 2 * NSEG_TOT) g_dc[i] = 0;
        return;
    }
    int bb = blockIdx.x - ZB;
    int b = bb >> 6;
    const float* W;
    if      (b == 0) W = W0; else if (b == 1) W = W1;
    else if (b == 2) W = W2; else if (b == 3) W = W3;
    else if (b == 4) W = W4; else if (b == 5) W = W5;
    else if (b == 6) W = W6; else              W = W7;
    unsigned char* img = imgbase + (size_t)b * WIMGSZ;
    int i = (bb & 63) * 256 + threadIdx.x;
    int n = i >> 7, k = i & 127;
    float w = W[k * 128 + n];
    __nv_bfloat16 h = __float2bfloat16(w);
    __nv_bfloat16 l = __float2bfloat16(w - __bfloat162float(h));
    *(uint16_t*)(img + n * WROW + k * 2) = __bfloat16_as_ushort(h);
    *(uint16_t*)(img + WLO + n * WROW + k * 2) = __bfloat16_as_ushort(l);
}

// ---------------- CSR build ----------------
__global__ void hist3(const int* __restrict__ d1, const int* __restrict__ d2,
                      const int* __restrict__ d3, int E1, int E2, int E3) {
    int i = blockIdx.x * 256 + threadIdx.x;
    if (i < E1) atomicAdd(g_dc + d1[i], 1);
    else if (i < E1 + E2) atomicAdd(g_dc + SEG_GS + d2[i - E1], 1);
    else if (i < E1 + E2 + E3) atomicAdd(g_dc + SEG_GG + d3[i - E1 - E2], 1);
}
__device__ __forceinline__ void seg_map(int b, int& degoff, int& nd, int& boff, int& lb) {
    if (b < NB_SG)            { degoff = 0;      nd = N_GENE; boff = 0;             lb = b; }
    else if (b < NB_SG+NB_GS) { degoff = SEG_GS; nd = N_SNP;  boff = NB_SG;         lb = b - NB_SG; }
    else                      { degoff = SEG_GG; nd = N_GENE; boff = NB_SG + NB_GS; lb = b - NB_SG - NB_GS; }
}
__global__ void bsum3() {
    __shared__ int sw[32];
    int degoff, nd, boff, lb;
    seg_map(blockIdx.x, degoff, nd, boff, lb);
    int i = lb * 1024 + threadIdx.x;
    int v = (i < nd) ? g_dc[degoff + i] : 0;
#pragma unroll
    for (int o = 16; o; o >>= 1) v += __shfl_xor_sync(0xffffffffu, v, o);
    if ((threadIdx.x & 31) == 0) sw[threadIdx.x >> 5] = v;
    __syncthreads();
    if (threadIdx.x < 32) {
        int t = sw[threadIdx.x];
#pragma unroll
        for (int o = 16; o; o >>= 1) t += __shfl_xor_sync(0xffffffffu, t, o);
        if (threadIdx.x == 0) g_bsum[boff + lb] = t;
    }
}
// scan3 now computes its own block base from g_bsum prefix (no bscan kernel).
__global__ void scan3() {
    __shared__ int sm[1024];
    __shared__ int sbase;
    int degoff, nd, boff, lb;
    seg_map(blockIdx.x, degoff, nd, boff, lb);
    int* rp = (blockIdx.x < NB_SG) ? g_rp_sg
            : (blockIdx.x < NB_SG + NB_GS) ? g_rp_gs : g_rp_gg;
    int tid = threadIdx.x;
    if (tid == 0) sbase = 0;
    __syncthreads();
    if (tid < lb) atomicAdd(&sbase, g_bsum[boff + tid]);
    int i = lb * 1024 + tid;
    int v = (i < nd) ? g_dc[degoff + i] : 0;
    sm[tid] = v;
    __syncthreads();
#pragma unroll
    for (int off = 1; off < 1024; off <<= 1) {
        int t = (tid >= off) ? sm[tid - off] : 0;
        __syncthreads();
        sm[tid] += t;
        __syncthreads();
    }
    int incl = sm[tid];
    int base = sbase;
    if (i < nd) rp[i] = base + incl - v;
    if (i == nd - 1) rp[nd] = base + incl;
}
__global__ void scatter3(const int* __restrict__ s1, const int* __restrict__ d1,
                         const int* __restrict__ s2, const int* __restrict__ d2,
                         const int* __restrict__ s3, const int* __restrict__ d3,
                         int E1, int E2, int E3) {
    int i = blockIdx.x * 256 + threadIdx.x;
    if (i < E1) {
        int d = d1[i];
        g_ss_sg[g_rp_sg[d] + atomicAdd(g_dc + NSEG_TOT + d, 1)] = s1[i];
    } else if (i < E1 + E2) {
        int e = i - E1, d = d2[e];
        g_ss_gs[g_rp_gs[d] + atomicAdd(g_dc + NSEG_TOT + SEG_GS + d, 1)] = s2[e];
    } else if (i < E1 + E2 + E3) {
        int e = i - E1 - E2, d = d3[e];
        g_ss_gg[g_rp_gg[d] + atomicAdd(g_dc + NSEG_TOT + SEG_GG + d, 1)] = s3[e];
    }
}

// ---------------- merged projection GEMM: snp + gene in one launch ----------------
#define TG_SMEM1 (WIMGSZ + 16)

__global__ void __launch_bounds__(256) proj_h(
    const float* __restrict__ As, const float* __restrict__ Ag,
    const unsigned char* __restrict__ imgS, const unsigned char* __restrict__ imgG,
    const float* __restrict__ bS, const float* __restrict__ bG,
    const float* __restrict__ a_src, const float* __restrict__ a_dst,
    int l, int nsblk)
{
    extern __shared__ unsigned char smem[];
    const int tid = threadIdx.x, wid = tid >> 5, lane = tid & 31;
    const int g = lane >> 2, tig = lane & 3;
    const bool is_snp = blockIdx.x < nsblk;
    const int blk = is_snp ? blockIdx.x : blockIdx.x - nsblk;
    const float* A = is_snp ? As : Ag;
    const unsigned char* Bimg = is_snp ? imgS : imgG;
    const float* bias = is_snp ? bS : bG;
    const int M = is_snp ? N_SNP : N_GENE;
    __half* Ch = is_snp ? g_hsh : g_hgh;

    {
        const uint4* src = (const uint4*)Bimg;
        uint4* dst = (uint4*)smem;
#pragma unroll
        for (int i = 0; i < 17; i++) {
            int idx = tid + 256 * i;
            if (idx < WIMGSZ / 16) dst[idx] = src[idx];
        }
    }
    __syncthreads();

    const int rowA = blk * 128 + wid * 16 + g;
    const int rowB = rowA + 8;
    const bool vA = rowA < M, vB = rowB < M;

    float4 acc[16];
#pragma unroll
    for (int nt = 0; nt < 16; nt++) acc[nt] = make_float4(0.f, 0.f, 0.f, 0.f);
    gemm_core(A, rowA, rowB, vA, vB, smem, lane, acc);

#pragma unroll
    for (int nt = 0; nt < 16; nt++) {
        int col = nt * 8 + 2 * tig;
        float b0 = bias[col], b1 = bias[col + 1];
        acc[nt].x += b0; acc[nt].y += b1;
        acc[nt].z += b0; acc[nt].w += b1;
    }

#pragma unroll
    for (int nt = 0; nt < 16; nt++) {
        int col = nt * 8 + 2 * tig;
        if (vA) *((__half2*)(Ch + (size_t)rowA * 128 + col)) = __floats2half2_rn(acc[nt].x, acc[nt].y);
        if (vB) *((__half2*)(Ch + (size_t)rowB * 128 + col)) = __floats2half2_rn(acc[nt].z, acc[nt].w);
    }

    const float* vv[4];
    float* sb[4];
    int nv;
    if (is_snp) {
        nv = 2;
        vv[0] = a_src + (l * 3 + 0) * 128; sb[0] = g_ssrc_sg;
        vv[1] = a_dst + (l * 3 + 1) * 128; sb[1] = g_sdst_gs;
        vv[2] = nullptr; vv[3] = nullptr;
    } else {
        nv = 4;
        vv[0] = a_dst + (l * 3 + 0) * 128; sb[0] = g_sdst_sg;
        vv[1] = a_src + (l * 3 + 1) * 128; sb[1] = g_ssrc_gs;
        vv[2] = a_src + (l * 3 + 2) * 128; sb[2] = g_ssrc_gg;
        vv[3] = a_dst + (l * 3 + 2) * 128; sb[3] = g_sdst_gg;
    }
#pragma unroll
    for (int v = 0; v < 4; v++) {
        if (v < nv) {
#pragma unroll
            for (int hd = 0; hd < 8; hd++) {
                float a0 = __ldg(vv[v] + 16 * hd + 2 * tig);
                float a1 = __ldg(vv[v] + 16 * hd + 2 * tig + 1);
                float a2 = __ldg(vv[v] + 16 * hd + 8 + 2 * tig);
                float a3 = __ldg(vv[v] + 16 * hd + 8 + 2 * tig + 1);
                float pA = acc[2*hd].x * a0 + acc[2*hd].y * a1
                         + acc[2*hd+1].x * a2 + acc[2*hd+1].y * a3;
                float pB = acc[2*hd].z * a0 + acc[2*hd].w * a1
                         + acc[2*hd+1].z * a2 + acc[2*hd+1].w * a3;
                pA += __shfl_xor_sync(0xffffffffu, pA, 1);
                pA += __shfl_xor_sync(0xffffffffu, pA, 2);
                pB += __shfl_xor_sync(0xffffffffu, pB, 1);
                pB += __shfl_xor_sync(0xffffffffu, pB, 2);
                if (tig == 0) {
                    if (vA) sb[v][rowA * 8 + hd] = pA;
                    if (vB) sb[v][rowB * 8 + hd] = pB;
                }
            }
        }
    }
}

// ---------------- semantic GEMM: tanh colsum partials (o_sg | o_gg merged) ----------
#define TG_SMEM_SEM (WIMGSZ + 512)

__global__ void __launch_bounds__(256) tgemm_sem(
    const unsigned char* __restrict__ Bimg, const float* __restrict__ bias, int nhalf)
{
    extern __shared__ unsigned char smem[];
    float* scs = (float*)(smem + WIMGSZ);
    const int tid = threadIdx.x, wid = tid >> 5, lane = tid & 31;
    const int g = lane >> 2, tig = lane & 3;
    int blk = blockIdx.x;
    const float* A = g_o_sg;
    if (blk >= nhalf) { A = g_o_gg; blk -= nhalf; }

    {
        const uint4* src = (const uint4*)Bimg;
        uint4* dst = (uint4*)smem;
#pragma unroll
        for (int i = 0; i < 17; i++) {
            int idx = tid + 256 * i;
            if (idx < WIMGSZ / 16) dst[idx] = src[idx];
        }
    }
    if (tid < 128) scs[tid] = 0.f;
    __syncthreads();

    const int rowA = blk * 128 + wid * 16 + g;
    const int rowB = rowA + 8;
    const bool vA = rowA < N_GENE, vB = rowB < N_GENE;

    float4 acc[16];
#pragma unroll
    for (int nt = 0; nt < 16; nt++) acc[nt] = make_float4(0.f, 0.f, 0.f, 0.f);
    gemm_core(A, rowA, rowB, vA, vB, smem, lane, acc);

#pragma unroll
    for (int nt = 0; nt < 16; nt++) {
        int col = nt * 8 + 2 * tig;
        float b0 = bias[col], b1 = bias[col + 1];
        float s0 = 0.f, s1 = 0.f;
        if (vA) { s0 += tanhf(acc[nt].x + b0); s1 += tanhf(acc[nt].y + b1); }
        if (vB) { s0 += tanhf(acc[nt].z + b0); s1 += tanhf(acc[nt].w + b1); }
        atomicAdd(scs + col, s0);
        atomicAdd(scs + col + 1, s1);
    }
    __syncthreads();
    if (tid < 128) g_sempart[(size_t)blockIdx.x * 128 + tid] = scs[tid];
}

// ---------------- final fused MLP ----------------
#define TG_SMEM_FIN (2 * WIMGSZ)

__global__ void __launch_bounds__(256) final2(
    const float* __restrict__ A,
    const unsigned char* __restrict__ img1, const unsigned char* __restrict__ img2,
    const float* __restrict__ b1, const float* __restrict__ b2v,
    const float* __restrict__ W2, const float* __restrict__ b2,
    float* __restrict__ outp, int M)
{
    extern __shared__ unsigned char smem[];
    const int tid = threadIdx.x, wid = tid >> 5, lane = tid & 31;
    const int g = lane >> 2, tig = lane & 3;

    {
        const uint4* s1 = (const uint4*)img1;
        const uint4* s2 = (const uint4*)img2;
        uint4* d1 = (uint4*)smem;
        uint4* d2 = (uint4*)(smem + WIMGSZ);
#pragma unroll
        for (int i = 0; i < 17; i++) {
            int idx = tid + 256 * i;
            if (idx < WIMGSZ / 16) { d1[idx] = s1[idx]; d2[idx] = s2[idx]; }
        }
    }
    __syncthreads();

    const int rowA = blockIdx.x * 128 + wid * 16 + g;
    const int rowB = rowA + 8;
    const bool vA = rowA < M, vB = rowB < M;

    float4 acc[16];
#pragma unroll
    for (int nt = 0; nt < 16; nt++) acc[nt] = make_float4(0.f, 0.f, 0.f, 0.f);
    gemm_core(A, rowA, rowB, vA, vB, smem, lane, acc);

#pragma unroll
    for (int nt = 0; nt < 16; nt++) {
        int col = nt * 8 + 2 * tig;
        float c0 = b1[col], c1 = b1[col + 1];
        acc[nt].x = fmaxf(acc[nt].x + c0, 0.f);
        acc[nt].y = fmaxf(acc[nt].y + c1, 0.f);
        acc[nt].z = fmaxf(acc[nt].z + c0, 0.f);
        acc[nt].w = fmaxf(acc[nt].w + c1, 0.f);
    }

    float4 acc2[16];
#pragma unroll
    for (int nt = 0; nt < 16; nt++) acc2[nt] = make_float4(0.f, 0.f, 0.f, 0.f);
    gemm_core_reg(acc, smem + WIMGSZ, lane, acc2);

    float pA0 = 0.f, pA1 = 0.f, pB0 = 0.f, pB1 = 0.f;
#pragma unroll
    for (int nt = 0; nt < 16; nt++) {
        int col = nt * 8 + 2 * tig;
        float c0 = b2v[col], c1 = b2v[col + 1];
        float rx = fmaxf(acc2[nt].x + c0, 0.f), ry = fmaxf(acc2[nt].y + c1, 0.f);
        float rz = fmaxf(acc2[nt].z + c0, 0.f), rw = fmaxf(acc2[nt].w + c1, 0.f);
        float w00 = __ldg(W2 + col * 2), w01 = __ldg(W2 + col * 2 + 1);
        float w10 = __ldg(W2 + (col + 1) * 2), w11 = __ldg(W2 + (col + 1) * 2 + 1);
        pA0 += rx * w00 + ry * w10; pA1 += rx * w01 + ry * w11;
        pB0 += rz * w00 + rw * w10; pB1 += rz * w01 + rw * w11;
    }
    pA0 += __shfl_xor_sync(0xffffffffu, pA0, 1); pA0 += __shfl_xor_sync(0xffffffffu, pA0, 2);
    pA1 += __shfl_xor_sync(0xffffffffu, pA1, 1); pA1 += __shfl_xor_sync(0xffffffffu, pA1, 2);
    pB0 += __shfl_xor_sync(0xffffffffu, pB0, 1); pB0 += __shfl_xor_sync(0xffffffffu, pB0, 2);
    pB1 += __shfl_xor_sync(0xffffffffu, pB1, 1); pB1 += __shfl_xor_sync(0xffffffffu, pB1, 2);
    if (tig == 0) {
        if (vA) { outp[(size_t)rowA * 2] = pA0 + b2[0]; outp[(size_t)rowA * 2 + 1] = pA1 + b2[1]; }
        if (vB) { outp[(size_t)rowB * 2] = pB0 + b2[0]; outp[(size_t)rowB * 2 + 1] = pB1 + b2[1]; }
    }
}

// ---------------- CSR aggregation: warp-batched indices, fused snp LN ----------------
__global__ void __launch_bounds__(256) agg3(
    const float* __restrict__ ln_gp, const float* __restrict__ ln_bp,
    const float* __restrict__ fw, int layer1)
{
    int w = blockIdx.x * 8 + (threadIdx.x >> 5);
    const __half* hsrc;
    const float *ssrc, *sdst;
    const int *rp, *ss;
    float* out;
    const float* prev = nullptr;
    int d;
    bool fuse = false;
    if (w < N_GENE) {
        d = w; hsrc = g_hsh; ssrc = g_ssrc_sg; sdst = g_sdst_sg;
        rp = g_rp_sg; ss = g_ss_sg; out = g_o_sg;
    } else if (w < N_GENE + N_SNP) {
        d = w - N_GENE; hsrc = g_hgh; ssrc = g_ssrc_gs; sdst = g_sdst_gs;
        rp = g_rp_gs; ss = g_ss_gs;
        fuse = true;
        prev = layer1 ? g_out_s0 : nullptr;
        out = layer1 ? g_buf1 : g_out_s0;
    } else if (w < 2 * N_GENE + N_SNP) {
        d = w - (N_GENE + N_SNP); hsrc = g_hgh; ssrc = g_ssrc_gg; sdst = g_sdst_gg;
        rp = g_rp_gg; ss = g_ss_gg; out = g_o_gg;
    } else return;

    const int lane = threadIdx.x & 31, hw = lane >> 4, l16 = lane & 15, hd = l16 >> 1;
    float sdh = __ldg(sdst + d * 8 + hd);
    int beg = __ldg(rp + d), end = __ldg(rp + d + 1);

    float acc[8];
#pragma unroll
    for (int j = 0; j < 8; j++) acc[j] = 0.f;
    float se = 0.f;

    for (int base = beg; base < end; base += 32) {
        int cnt = end - base; if (cnt > 32) cnt = 32;
        int my = (base + lane < end) ? __ldg(ss + base + lane) : 0;
        // uniform trip count over pairs; half-warps take jj = j + hw
        for (int j = 0; j < cnt; j += 2) {
            int jj = j + hw;
            int jc = jj < cnt ? jj : cnt - 1;
            int s = __shfl_sync(0xffffffffu, my, jc);
            if (jj < cnt) {
                float a = __ldg(ssrc + s * 8 + hd) + sdh;
                uint4 u = *((const uint4*)(hsrc + (size_t)s * 128) + l16);
                a = a > 0.f ? a : NEG * a;
                float e = __expf(a);
                float2 f0 = __half22float2(*(__half2*)&u.x);
                float2 f1 = __half22float2(*(__half2*)&u.y);
                float2 f2 = __half22float2(*(__half2*)&u.z);
                float2 f3 = __half22float2(*(__half2*)&u.w);
                acc[0] = fmaf(e, f0.x, acc[0]); acc[1] = fmaf(e, f0.y, acc[1]);
                acc[2] = fmaf(e, f1.x, acc[2]); acc[3] = fmaf(e, f1.y, acc[3]);
                acc[4] = fmaf(e, f2.x, acc[4]); acc[5] = fmaf(e, f2.y, acc[5]);
                acc[6] = fmaf(e, f3.x, acc[6]); acc[7] = fmaf(e, f3.y, acc[7]);
                se += e;
            }
        }
    }
    se += __shfl_xor_sync(0xffffffffu, se, 16);
#pragma unroll
    for (int j = 0; j < 8; j++) acc[j] += __shfl_xor_sync(0xffffffffu, acc[j], 16);
    float inv = 1.f / (se + 1e-16f);
    float r[8];
#pragma unroll
    for (int j = 0; j < 8; j++) r[j] = fmaxf(acc[j] * inv, 0.f);

    if (!fuse) {
        if (hw == 0) {
            float4* op = (float4*)(out + (size_t)d * 128 + l16 * 8);
            op[0] = make_float4(r[0], r[1], r[2], r[3]);
            op[1] = make_float4(r[4], r[5], r[6], r[7]);
        }
        return;
    }

    float ps = r[0] + r[1] + r[2] + r[3] + r[4] + r[5] + r[6] + r[7];
#pragma unroll
    for (int o = 8; o; o >>= 1) ps += __shfl_xor_sync(0xffffffffu, ps, o);
    float mu = ps * (1.f / 128.f);
    float pv = 0.f;
#pragma unroll
    for (int j = 0; j < 8; j++) { float dl = r[j] - mu; pv += dl * dl; }
#pragma unroll
    for (int o = 8; o; o >>= 1) pv += __shfl_xor_sync(0xffffffffu, pv, o);
    float rs = rsqrtf(pv * (1.f / 128.f) + 1e-5f);
    if (hw == 0) {
        float4 g0 = __ldg((const float4*)ln_gp + l16 * 2);
        float4 g1 = __ldg((const float4*)ln_gp + l16 * 2 + 1);
        float4 b0 = __ldg((const float4*)ln_bp + l16 * 2);
        float4 b1 = __ldg((const float4*)ln_bp + l16 * 2 + 1);
        float4 o0, o1;
        o0.x = (r[0] - mu) * rs * g0.x + b0.x;
        o0.y = (r[1] - mu) * rs * g0.y + b0.y;
        o0.z = (r[2] - mu) * rs * g0.z + b0.z;
        o0.w = (r[3] - mu) * rs * g0.w + b0.w;
        o1.x = (r[4] - mu) * rs * g1.x + b1.x;
        o1.y = (r[5] - mu) * rs * g1.y + b1.y;
        o1.z = (r[6] - mu) * rs * g1.z + b1.z;
        o1.w = (r[7] - mu) * rs * g1.w + b1.w;
        if (prev) {
            float w0 = fw[0], w1 = fw[1];
            float iw = 1.f / (w0 + w1);
            float4 p0 = *((const float4*)(prev + (size_t)d * 128 + l16 * 8));
            float4 p1 = *((const float4*)(prev + (size_t)d * 128 + l16 * 8) + 1);
            o0.x = (w0 * p0.x + w1 * o0.x) * iw;
            o0.y = (w0 * p0.y + w1 * o0.y) * iw;
            o0.z = (w0 * p0.z + w1 * o0.z) * iw;
            o0.w = (w0 * p0.w + w1 * o0.w) * iw;
            o1.x = (w0 * p1.x + w1 * o1.x) * iw;
            o1.y = (w0 * p1.y + w1 * o1.y) * iw;
            o1.z = (w0 * p1.z + w1 * o1.z) * iw;
            o1.w = (w0 * p1.w + w1 * o1.w) * iw;
        }
        float4* op = (float4*)(out + (size_t)d * 128 + l16 * 8);
        op[0] = o0; op[1] = o1;
    }
}

// ---------------- gene combine + inline semantic softmax + LayerNorm ----------------
// Each block first reduces the semantic partials to attn (redundantly), then
// processes 64 gene rows (8 per warp).
__global__ void __launch_bounds__(256) combine_all(
    const float* __restrict__ q,
    const float* __restrict__ ln_gp, const float* __restrict__ ln_bp,
    const float* __restrict__ fw, int layer1)
{
    __shared__ float sw[8];
    __shared__ float sattn[2];
    const int tid = threadIdx.x, wid = tid >> 5, lane = tid & 31;

    // inline semantic reduction: thread t handles (m = t>>7, col = t&127)
    {
        int m = tid >> 7, col = tid & 127;
        float s = 0.f;
        const float* part = g_sempart + (size_t)m * TG_BLKS * 128 + col;
#pragma unroll 4
        for (int b = 0; b < TG_BLKS; b++) s += part[b * 128];
        float v = __ldg(q + col) * (s / 20000.f);
#pragma unroll
        for (int o = 16; o; o >>= 1) v += __shfl_xor_sync(0xffffffffu, v, o);
        if (lane == 0) sw[wid] = v;
        __syncthreads();
        if (tid == 0) {
            float s0 = sw[0] + sw[1] + sw[2] + sw[3];
            float s1 = sw[4] + sw[5] + sw[6] + sw[7];
            float mx = fmaxf(s0, s1);
            float e0 = __expf(s0 - mx), e1 = __expf(s1 - mx);
            float iv = 1.f / (e0 + e1);
            sattn[0] = e0 * iv; sattn[1] = e1 * iv;
        }
        __syncthreads();
    }
    const float a0 = sattn[0], a1 = sattn[1];
    const float* prev = layer1 ? g_out_g0 : nullptr;
    float* outb = layer1 ? (g_buf1 + (size_t)N_SNP * 128) : g_out_g0;

#pragma unroll
    for (int k = 0; k < 8; k++) {
        int n = blockIdx.x * 64 + wid * 8 + k;
        if (n >= N_GENE) break;
        float4 v = *((const float4*)(g_o_sg + (size_t)n * 128) + lane);
        float4 u = *((const float4*)(g_o_gg + (size_t)n * 128) + lane);
        v.x = a0 * v.x + a1 * u.x;
        v.y = a0 * v.y + a1 * u.y;
        v.z = a0 * v.z + a1 * u.z;
        v.w = a0 * v.w + a1 * u.w;
        float s = v.x + v.y + v.z + v.w;
#pragma unroll
        for (int o = 16; o; o >>= 1) s += __shfl_xor_sync(0xffffffffu, s, o);
        float mu = s * (1.f / 128.f);
        float dx = v.x - mu, dy = v.y - mu, dz = v.z - mu, dw = v.w - mu;
        float qv = dx * dx + dy * dy + dz * dz + dw * dw;
#pragma unroll
        for (int o = 16; o; o >>= 1) qv += __shfl_xor_sync(0xffffffffu, qv, o);
        float rs = rsqrtf(qv * (1.f / 128.f) + 1e-5f);
        float4 g4 = __ldg((const float4*)ln_gp + lane);
        float4 b4 = __ldg((const float4*)ln_bp + lane);
        float4 r;
        r.x = dx * rs * g4.x + b4.x;
        r.y = dy * rs * g4.y + b4.y;
        r.z = dz * rs * g4.z + b4.z;
        r.w = dw * rs * g4.w + b4.w;
        if (prev) {
            float w0 = fw[0], w1 = fw[1];
            float iv = 1.f / (w0 + w1);
            float4 p = *((const float4*)(prev + (size_t)n * 128) + lane);
            r.x = (w0 * p.x + w1 * r.x) * iv;
            r.y = (w0 * p.y + w1 * r.y) * iv;
            r.z = (w0 * p.z + w1 * r.z) * iv;
            r.w = (w0 * p.w + w1 * r.w) * iv;
        }
        *((float4*)(outb + (size_t)n * 128) + lane) = r;
    }
}

static inline int cdiv(long a, int b) { return (int)((a + b - 1) / b); }

extern "C" void kernel_launch(void* const* d_in, const int* in_sizes, int n_in,
                              void* d_out, int out_size)
{
    const float* x_snp  = (const float*)d_in[0];
    const float* x_gene = (const float*)d_in[1];
    const float* Wp_snp = (const float*)d_in[2];
    const float* bp_snp = (const float*)d_in[3];
    const float* Wp_gene= (const float*)d_in[4];
    const float* bp_gene= (const float*)d_in[5];
    const float* a_src  = (const float*)d_in[6];
    const float* a_dst  = (const float*)d_in[7];
    const float* Wk     = (const float*)d_in[8];
    const float* bk     = (const float*)d_in[9];
    const float* qvp    = (const float*)d_in[10];
    const float* ln_g   = (const float*)d_in[11];
    const float* ln_b   = (const float*)d_in[12];
    const float* fw     = (const float*)d_in[13];
    const float* Wfp    = (const float*)d_in[14];
    const float* bfp    = (const float*)d_in[15];
    const float* Wo1    = (const float*)d_in[16];
    const float* bo1    = (const float*)d_in[17];
    const float* Wo2    = (const float*)d_in[18];
    const float* bo2    = (const float*)d_in[19];
    const int* sg_s = (const int*)d_in[20];
    const int* sg_d = (const int*)d_in[21];
    const int* gs_s = (const int*)d_in[22];
    const int* gs_d = (const int*)d_in[23];
    const int* gg_s = (const int*)d_in[24];
    const int* gg_d = (const int*)d_in[25];
    const int E_sg = in_sizes[20], E_gs = in_sizes[22], E_gg = in_sizes[24];

    float *out_s0, *out_g0, *buf1;
    unsigned char* wimg;
    cudaGetSymbolAddress((void**)&out_s0, g_out_s0);
    cudaGetSymbolAddress((void**)&out_g0, g_out_g0);
    cudaGetSymbolAddress((void**)&buf1, g_buf1);
    cudaGetSymbolAddress((void**)&wimg, g_wimg);

    cudaFuncSetAttribute(proj_h, cudaFuncAttributeMaxDynamicSharedMemorySize, TG_SMEM1);
    cudaFuncSetAttribute(tgemm_sem, cudaFuncAttributeMaxDynamicSharedMemorySize, TG_SMEM_SEM);
    cudaFuncSetAttribute(final2, cudaFuncAttributeMaxDynamicSharedMemorySize, TG_SMEM_FIN);

    prep_k<<<ZB + 512, 256>>>(Wp_snp, Wp_snp + 16384, Wp_gene, Wp_gene + 16384,
                              Wk, Wk + 16384, Wfp, Wo1, wimg);

    const int E_tot = E_sg + E_gs + E_gg;
    hist3<<<cdiv(E_tot, 256), 256>>>(sg_d, gs_d, gg_d, E_sg, E_gs, E_gg);
    bsum3<<<NB_TOT, 1024>>>();
    scan3<<<NB_TOT, 1024>>>();
    scatter3<<<cdiv(E_tot, 256), 256>>>(sg_s, sg_d, gs_s, gs_d, gg_s, gg_d,
                                        E_sg, E_gs, E_gg);

    const int TS = cdiv(N_SNP, 128), TG = cdiv(N_GENE, 128), TA = cdiv(N_ALL, 128);

    for (int l = 0; l < 2; ++l) {
        const float* ins = l ? out_s0 : x_snp;
        const float* ing = l ? out_g0 : x_gene;

        proj_h<<<TS + TG, 256, TG_SMEM1>>>(ins, ing,
            wimg + l * WIMGSZ, wimg + (2 + l) * WIMGSZ,
            bp_snp + l * 128, bp_gene + l * 128, a_src, a_dst, l, TS);

        agg3<<<cdiv(2 * N_GENE + N_SNP, 8), 256>>>(ln_g + l * 128, ln_b + l * 128, fw, l);

        tgemm_sem<<<2 * TG, 256, TG_SMEM_SEM>>>(wimg + (4 + l) * WIMGSZ, bk + l * 128, TG);

        combine_all<<<cdiv(N_GENE, 64), 256>>>(qvp + l * 128,
            ln_g + l * 128, ln_b + l * 128, fw, l);
    }

    final2<<<TA, 256, TG_SMEM_FIN>>>(buf1, wimg + 6 * WIMGSZ, wimg + 7 * WIMGSZ,
                                     bfp, bo1, Wo2, bo2, (float*)d_out, N_ALL);
}

// round 12
// speedup vs baseline: 1.0533x; 1.0533x over previous
#include <cuda_runtime.h>
#include <cuda_bf16.h>
#include <cuda_fp16.h>
#include <cstdint>

#define N_SNP  100000
#define N_GENE 20000
#define N_ALL  120000
#define HID    128
#define NEG    0.2f

#define E_SG_MAX 500000
#define E_GS_MAX 500000
#define E_GG_MAX 150000

#define SEG_GS 20000
#define SEG_GG 120000
#define NSEG_TOT 140000
#define NB_SG 20
#define NB_GS 98
#define NB_GG 20
#define NB_TOT 138

#define TG_BLKS 157

#define WROW   272
#define WLO    34816
#define WIMGSZ 69632

// ---------------- device scratch ----------------
__device__ __half   g_hsh[N_SNP * HID];
__device__ __half   g_hgh[N_GENE * HID];
__device__ float    g_ssrc_sg[N_SNP * 8];
__device__ float    g_sdst_gs[N_SNP * 8];
__device__ float    g_sdst_sg[N_GENE * 8];
__device__ float    g_ssrc_gs[N_GENE * 8];
__device__ float    g_ssrc_gg[N_GENE * 8];
__device__ float    g_sdst_gg[N_GENE * 8];
__device__ float    g_o_sg[N_GENE * HID];
__device__ float    g_o_gg[N_GENE * HID];
__device__ float    g_out_s0[N_SNP * HID];
__device__ float    g_out_g0[N_GENE * HID];
__device__ float    g_sempart[2 * TG_BLKS * HID];
__device__ float    g_attn[2];
__device__ float    g_buf1[N_ALL * HID];
__device__ __align__(16) unsigned char g_wimg[8 * WIMGSZ];
__device__ int g_rp_sg[N_GENE + 1];
__device__ int g_rp_gs[N_SNP + 1];
__device__ int g_rp_gg[N_GENE + 1];
__device__ int g_dc[2 * NSEG_TOT];
__device__ int g_bsum[NB_TOT + 4];
__device__ int g_ss_sg[E_SG_MAX];
__device__ int g_ss_gs[E_GS_MAX];
__device__ int g_ss_gg[E_GG_MAX];

__device__ __forceinline__ uint32_t pack_bf(float x, float y) {
    __nv_bfloat162 t = __floats2bfloat162_rn(x, y);
    return *(uint32_t*)&t;
}
__device__ __forceinline__ void mma_bf16(float4& c, uint32_t a0, uint32_t a1,
                                         uint32_t a2, uint32_t a3,
                                         uint32_t b0, uint32_t b1) {
    asm volatile("mma.sync.aligned.m16n8k16.row.col.f32.bf16.bf16.f32 "
                 "{%0,%1,%2,%3}, {%4,%5,%6,%7}, {%8,%9}, {%0,%1,%2,%3};"
                 : "+f"(c.x), "+f"(c.y), "+f"(c.z), "+f"(c.w)
                 : "r"(a0), "r"(a1), "r"(a2), "r"(a3), "r"(b0), "r"(b1));
}

// Core GEMM: 16-row strip pair per warp from gmem fp32 A vs smem weight image.
__device__ __forceinline__ void gemm_core(
    const float* __restrict__ A, int rowA, int rowB, bool vA, bool vB,
    const unsigned char* sm, int lane, float4 acc[16])
{
    const int g = lane >> 2, tig = lane & 3;
    const float* ArA = A + (size_t)rowA * 128;
    const float* ArB = A + (size_t)rowB * 128;
#pragma unroll
    for (int ks = 0; ks < 8; ks++) {
        const int k0 = ks * 16;
        float2 p00 = make_float2(0.f, 0.f), p01 = p00, p10 = p00, p11 = p00;
        if (vA) {
            p00 = *(const float2*)(ArA + k0 + 2 * tig);
            p01 = *(const float2*)(ArA + k0 + 2 * tig + 8);
        }
        if (vB) {
            p10 = *(const float2*)(ArB + k0 + 2 * tig);
            p11 = *(const float2*)(ArB + k0 + 2 * tig + 8);
        }
        uint32_t ah0 = pack_bf(p00.x, p00.y), ah1 = pack_bf(p10.x, p10.y);
        uint32_t ah2 = pack_bf(p01.x, p01.y), ah3 = pack_bf(p11.x, p11.y);
        __nv_bfloat162 h00 = *(__nv_bfloat162*)&ah0, h10 = *(__nv_bfloat162*)&ah1;
        __nv_bfloat162 h01 = *(__nv_bfloat162*)&ah2, h11 = *(__nv_bfloat162*)&ah3;
        uint32_t al0 = pack_bf(p00.x - __bfloat162float(h00.x), p00.y - __bfloat162float(h00.y));
        uint32_t al1 = pack_bf(p10.x - __bfloat162float(h10.x), p10.y - __bfloat162float(h10.y));
        uint32_t al2 = pack_bf(p01.x - __bfloat162float(h01.x), p01.y - __bfloat162float(h01.y));
        uint32_t al3 = pack_bf(p11.x - __bfloat162float(h11.x), p11.y - __bfloat162float(h11.y));

        const unsigned char* bh = sm + (size_t)g * WROW + (k0 + 2 * tig) * 2;
#pragma unroll
        for (int nt = 0; nt < 16; nt++) {
            uint32_t bh0 = *(const uint32_t*)(bh + nt * 8 * WROW);
            uint32_t bh1 = *(const uint32_t*)(bh + nt * 8 * WROW + 16);
            mma_bf16(acc[nt], ah0, ah1, ah2, ah3, bh0, bh1);
            mma_bf16(acc[nt], al0, al1, al2, al3, bh0, bh1);
            uint32_t bl0 = *(const uint32_t*)(bh + WLO + nt * 8 * WROW);
            uint32_t bl1 = *(const uint32_t*)(bh + WLO + nt * 8 * WROW + 16);
            mma_bf16(acc[nt], ah0, ah1, ah2, ah3, bl0, bl1);
        }
    }
}

// Second GEMM with A operand coming from register accumulators.
__device__ __forceinline__ void gemm_core_reg(
    const float4 a1[16], const unsigned char* sm, int lane, float4 acc[16])
{
    const int g = lane >> 2, tig = lane & 3;
#pragma unroll
    for (int kt = 0; kt < 8; kt++) {
        float x0 = a1[2*kt].x,   y0 = a1[2*kt].y;
        float x1 = a1[2*kt].z,   y1 = a1[2*kt].w;
        float x2 = a1[2*kt+1].x, y2 = a1[2*kt+1].y;
        float x3 = a1[2*kt+1].z, y3 = a1[2*kt+1].w;
        uint32_t ah0 = pack_bf(x0, y0), ah1 = pack_bf(x1, y1);
        uint32_t ah2 = pack_bf(x2, y2), ah3 = pack_bf(x3, y3);
        __nv_bfloat162 h0 = *(__nv_bfloat162*)&ah0, h1 = *(__nv_bfloat162*)&ah1;
        __nv_bfloat162 h2 = *(__nv_bfloat162*)&ah2, h3 = *(__nv_bfloat162*)&ah3;
        uint32_t al0 = pack_bf(x0 - __bfloat162float(h0.x), y0 - __bfloat162float(h0.y));
        uint32_t al1 = pack_bf(x1 - __bfloat162float(h1.x), y1 - __bfloat162float(h1.y));
        uint32_t al2 = pack_bf(x2 - __bfloat162float(h2.x), y2 - __bfloat162float(h2.y));
        uint32_t al3 = pack_bf(x3 - __bfloat162float(h3.x), y3 - __bfloat162float(h3.y));

        const unsigned char* bh = sm + (size_t)g * WROW + (kt * 16 + 2 * tig) * 2;
#pragma unroll
        for (int nt = 0; nt < 16; nt++) {
            uint32_t bh0 = *(const uint32_t*)(bh + nt * 8 * WROW);
            uint32_t bh1 = *(const uint32_t*)(bh + nt * 8 * WROW + 16);
            mma_bf16(acc[nt], ah0, ah1, ah2, ah3, bh0, bh1);
            mma_bf16(acc[nt], al0, al1, al2, al3, bh0, bh1);
            uint32_t bl0 = *(const uint32_t*)(bh + WLO + nt * 8 * WROW);
            uint32_t bl1 = *(const uint32_t*)(bh + WLO + nt * 8 * WROW + 16);
            mma_bf16(acc[nt], ah0, ah1, ah2, ah3, bl0, bl1);
        }
    }
}

// ---------------- prep: zero counters + weight images in ONE launch ----------------
#define ZB 1094   // cdiv(2*NSEG_TOT,256)
__global__ void prep_k(const float* __restrict__ W0, const float* __restrict__ W1,
                       const float* __restrict__ W2, const float* __restrict__ W3,
                       const float* __restrict__ W4, const float* __restrict__ W5,
                       const float* __restrict__ W6, const float* __restrict__ W7,
                       unsigned char* __restrict__ imgbase) {
    if (blockIdx.x < ZB) {
        int i = blockIdx.x * 256 + threadIdx.x;
        if (i < 2 * NSEG_TOT) g_dc[i] = 0;
        return;
    }
    int bb = blockIdx.x - ZB;
    int b = bb >> 6;
    const float* W;
    if      (b == 0) W = W0; else if (b == 1) W = W1;
    else if (b == 2) W = W2; else if (b == 3) W = W3;
    else if (b == 4) W = W4; else if (b == 5) W = W5;
    else if (b == 6) W = W6; else              W = W7;
    unsigned char* img = imgbase + (size_t)b * WIMGSZ;
    int i = (bb & 63) * 256 + threadIdx.x;
    int n = i >> 7, k = i & 127;
    float w = W[k * 128 + n];
    __nv_bfloat16 h = __float2bfloat16(w);
    __nv_bfloat16 l = __float2bfloat16(w - __bfloat162float(h));
    *(uint16_t*)(img + n * WROW + k * 2) = __bfloat16_as_ushort(h);
    *(uint16_t*)(img + WLO + n * WROW + k * 2) = __bfloat16_as_ushort(l);
}

// ---------------- CSR build ----------------
__global__ void hist3(const int* __restrict__ d1, const int* __restrict__ d2,
                      const int* __restrict__ d3, int E1, int E2, int E3) {
    int i = blockIdx.x * 256 + threadIdx.x;
    if (i < E1) atomicAdd(g_dc + d1[i], 1);
    else if (i < E1 + E2) atomicAdd(g_dc + SEG_GS + d2[i - E1], 1);
    else if (i < E1 + E2 + E3) atomicAdd(g_dc + SEG_GG + d3[i - E1 - E2], 1);
}
__device__ __forceinline__ void seg_map(int b, int& degoff, int& nd, int& boff, int& lb) {
    if (b < NB_SG)            { degoff = 0;      nd = N_GENE; boff = 0;             lb = b; }
    else if (b < NB_SG+NB_GS) { degoff = SEG_GS; nd = N_SNP;  boff = NB_SG;         lb = b - NB_SG; }
    else                      { degoff = SEG_GG; nd = N_GENE; boff = NB_SG + NB_GS; lb = b - NB_SG - NB_GS; }
}
__global__ void bsum3() {
    __shared__ int sw[32];
    int degoff, nd, boff, lb;
    seg_map(blockIdx.x, degoff, nd, boff, lb);
    int i = lb * 1024 + threadIdx.x;
    int v = (i < nd) ? g_dc[degoff + i] : 0;
#pragma unroll
    for (int o = 16; o; o >>= 1) v += __shfl_xor_sync(0xffffffffu, v, o);
    if ((threadIdx.x & 31) == 0) sw[threadIdx.x >> 5] = v;
    __syncthreads();
    if (threadIdx.x < 32) {
        int t = sw[threadIdx.x];
#pragma unroll
        for (int o = 16; o; o >>= 1) t += __shfl_xor_sync(0xffffffffu, t, o);
        if (threadIdx.x == 0) g_bsum[boff + lb] = t;
    }
}
// scan3 computes its own block base from g_bsum prefix (no bscan kernel).
__global__ void scan3() {
    __shared__ int sm[1024];
    __shared__ int sbase;
    int degoff, nd, boff, lb;
    seg_map(blockIdx.x, degoff, nd, boff, lb);
    int* rp = (blockIdx.x < NB_SG) ? g_rp_sg
            : (blockIdx.x < NB_SG + NB_GS) ? g_rp_gs : g_rp_gg;
    int tid = threadIdx.x;
    if (tid == 0) sbase = 0;
    __syncthreads();
    if (tid < lb) atomicAdd(&sbase, g_bsum[boff + tid]);
    int i = lb * 1024 + tid;
    int v = (i < nd) ? g_dc[degoff + i] : 0;
    sm[tid] = v;
    __syncthreads();
#pragma unroll
    for (int off = 1; off < 1024; off <<= 1) {
        int t = (tid >= off) ? sm[tid - off] : 0;
        __syncthreads();
        sm[tid] += t;
        __syncthreads();
    }
    int incl = sm[tid];
    int base = sbase;
    if (i < nd) rp[i] = base + incl - v;
    if (i == nd - 1) rp[nd] = base + incl;
}
__global__ void scatter3(const int* __restrict__ s1, const int* __restrict__ d1,
                         const int* __restrict__ s2, const int* __restrict__ d2,
                         const int* __restrict__ s3, const int* __restrict__ d3,
                         int E1, int E2, int E3) {
    int i = blockIdx.x * 256 + threadIdx.x;
    if (i < E1) {
        int d = d1[i];
        g_ss_sg[g_rp_sg[d] + atomicAdd(g_dc + NSEG_TOT + d, 1)] = s1[i];
    } else if (i < E1 + E2) {
        int e = i - E1, d = d2[e];
        g_ss_gs[g_rp_gs[d] + atomicAdd(g_dc + NSEG_TOT + SEG_GS + d, 1)] = s2[e];
    } else if (i < E1 + E2 + E3) {
        int e = i - E1 - E2, d = d3[e];
        g_ss_gg[g_rp_gg[d] + atomicAdd(g_dc + NSEG_TOT + SEG_GG + d, 1)] = s3[e];
    }
}

// ---------------- merged projection GEMM: snp + gene in one launch ----------------
#define TG_SMEM1 (WIMGSZ + 16)

__global__ void __launch_bounds__(256) proj_h(
    const float* __restrict__ As, const float* __restrict__ Ag,
    const unsigned char* __restrict__ imgS, const unsigned char* __restrict__ imgG,
    const float* __restrict__ bS, const float* __restrict__ bG,
    const float* __restrict__ a_src, const float* __restrict__ a_dst,
    int l, int nsblk)
{
    extern __shared__ unsigned char smem[];
    const int tid = threadIdx.x, wid = tid >> 5, lane = tid & 31;
    const int g = lane >> 2, tig = lane & 3;
    const bool is_snp = blockIdx.x < nsblk;
    const int blk = is_snp ? blockIdx.x : blockIdx.x - nsblk;
    const float* A = is_snp ? As : Ag;
    const unsigned char* Bimg = is_snp ? imgS : imgG;
    const float* bias = is_snp ? bS : bG;
    const int M = is_snp ? N_SNP : N_GENE;
    __half* Ch = is_snp ? g_hsh : g_hgh;

    {
        const uint4* src = (const uint4*)Bimg;
        uint4* dst = (uint4*)smem;
#pragma unroll
        for (int i = 0; i < 17; i++) {
            int idx = tid + 256 * i;
            if (idx < WIMGSZ / 16) dst[idx] = src[idx];
        }
    }
    __syncthreads();

    const int rowA = blk * 128 + wid * 16 + g;
    const int rowB = rowA + 8;
    const bool vA = rowA < M, vB = rowB < M;

    float4 acc[16];
#pragma unroll
    for (int nt = 0; nt < 16; nt++) acc[nt] = make_float4(0.f, 0.f, 0.f, 0.f);
    gemm_core(A, rowA, rowB, vA, vB, smem, lane, acc);

#pragma unroll
    for (int nt = 0; nt < 16; nt++) {
        int col = nt * 8 + 2 * tig;
        float b0 = bias[col], b1 = bias[col + 1];
        acc[nt].x += b0; acc[nt].y += b1;
        acc[nt].z += b0; acc[nt].w += b1;
    }

#pragma unroll
    for (int nt = 0; nt < 16; nt++) {
        int col = nt * 8 + 2 * tig;
        if (vA) *((__half2*)(Ch + (size_t)rowA * 128 + col)) = __floats2half2_rn(acc[nt].x, acc[nt].y);
        if (vB) *((__half2*)(Ch + (size_t)rowB * 128 + col)) = __floats2half2_rn(acc[nt].z, acc[nt].w);
    }

    const float* vv[4];
    float* sb[4];
    int nv;
    if (is_snp) {
        nv = 2;
        vv[0] = a_src + (l * 3 + 0) * 128; sb[0] = g_ssrc_sg;
        vv[1] = a_dst + (l * 3 + 1) * 128; sb[1] = g_sdst_gs;
        vv[2] = nullptr; vv[3] = nullptr;
    } else {
        nv = 4;
        vv[0] = a_dst + (l * 3 + 0) * 128; sb[0] = g_sdst_sg;
        vv[1] = a_src + (l * 3 + 1) * 128; sb[1] = g_ssrc_gs;
        vv[2] = a_src + (l * 3 + 2) * 128; sb[2] = g_ssrc_gg;
        vv[3] = a_dst + (l * 3 + 2) * 128; sb[3] = g_sdst_gg;
    }
#pragma unroll
    for (int v = 0; v < 4; v++) {
        if (v < nv) {
#pragma unroll
            for (int hd = 0; hd < 8; hd++) {
                float a0 = __ldg(vv[v] + 16 * hd + 2 * tig);
                float a1 = __ldg(vv[v] + 16 * hd + 2 * tig + 1);
                float a2 = __ldg(vv[v] + 16 * hd + 8 + 2 * tig);
                float a3 = __ldg(vv[v] + 16 * hd + 8 + 2 * tig + 1);
                float pA = acc[2*hd].x * a0 + acc[2*hd].y * a1
                         + acc[2*hd+1].x * a2 + acc[2*hd+1].y * a3;
                float pB = acc[2*hd].z * a0 + acc[2*hd].w * a1
                         + acc[2*hd+1].z * a2 + acc[2*hd+1].w * a3;
                pA += __shfl_xor_sync(0xffffffffu, pA, 1);
                pA += __shfl_xor_sync(0xffffffffu, pA, 2);
                pB += __shfl_xor_sync(0xffffffffu, pB, 1);
                pB += __shfl_xor_sync(0xffffffffu, pB, 2);
                if (tig == 0) {
                    if (vA) sb[v][rowA * 8 + hd] = pA;
                    if (vB) sb[v][rowB * 8 + hd] = pB;
                }
            }
        }
    }
}

// ---------------- semantic GEMM: tanh colsum partials (o_sg | o_gg merged) ----------
#define TG_SMEM_SEM (WIMGSZ + 512)

__global__ void __launch_bounds__(256) tgemm_sem(
    const unsigned char* __restrict__ Bimg, const float* __restrict__ bias, int nhalf)
{
    extern __shared__ unsigned char smem[];
    float* scs = (float*)(smem + WIMGSZ);
    const int tid = threadIdx.x, wid = tid >> 5, lane = tid & 31;
    const int g = lane >> 2, tig = lane & 3;
    int blk = blockIdx.x;
    const float* A = g_o_sg;
    if (blk >= nhalf) { A = g_o_gg; blk -= nhalf; }

    {
        const uint4* src = (const uint4*)Bimg;
        uint4* dst = (uint4*)smem;
#pragma unroll
        for (int i = 0; i < 17; i++) {
            int idx = tid + 256 * i;
            if (idx < WIMGSZ / 16) dst[idx] = src[idx];
        }
    }
    if (tid < 128) scs[tid] = 0.f;
    __syncthreads();

    const int rowA = blk * 128 + wid * 16 + g;
    const int rowB = rowA + 8;
    const bool vA = rowA < N_GENE, vB = rowB < N_GENE;

    float4 acc[16];
#pragma unroll
    for (int nt = 0; nt < 16; nt++) acc[nt] = make_float4(0.f, 0.f, 0.f, 0.f);
    gemm_core(A, rowA, rowB, vA, vB, smem, lane, acc);

#pragma unroll
    for (int nt = 0; nt < 16; nt++) {
        int col = nt * 8 + 2 * tig;
        float b0 = bias[col], b1 = bias[col + 1];
        float s0 = 0.f, s1 = 0.f;
        if (vA) { s0 += tanhf(acc[nt].x + b0); s1 += tanhf(acc[nt].y + b1); }
        if (vB) { s0 += tanhf(acc[nt].z + b0); s1 += tanhf(acc[nt].w + b1); }
        atomicAdd(scs + col, s0);
        atomicAdd(scs + col + 1, s1);
    }
    __syncthreads();
    if (tid < 128) g_sempart[(size_t)blockIdx.x * 128 + tid] = scs[tid];
}

// ---------------- final fused MLP ----------------
#define TG_SMEM_FIN (2 * WIMGSZ)

__global__ void __launch_bounds__(256) final2(
    const float* __restrict__ A,
    const unsigned char* __restrict__ img1, const unsigned char* __restrict__ img2,
    const float* __restrict__ b1, const float* __restrict__ b2v,
    const float* __restrict__ W2, const float* __restrict__ b2,
    float* __restrict__ outp, int M)
{
    extern __shared__ unsigned char smem[];
    const int tid = threadIdx.x, wid = tid >> 5, lane = tid & 31;
    const int g = lane >> 2, tig = lane & 3;

    {
        const uint4* s1 = (const uint4*)img1;
        const uint4* s2 = (const uint4*)img2;
        uint4* d1 = (uint4*)smem;
        uint4* d2 = (uint4*)(smem + WIMGSZ);
#pragma unroll
        for (int i = 0; i < 17; i++) {
            int idx = tid + 256 * i;
            if (idx < WIMGSZ / 16) { d1[idx] = s1[idx]; d2[idx] = s2[idx]; }
        }
    }
    __syncthreads();

    const int rowA = blockIdx.x * 128 + wid * 16 + g;
    const int rowB = rowA + 8;
    const bool vA = rowA < M, vB = rowB < M;

    float4 acc[16];
#pragma unroll
    for (int nt = 0; nt < 16; nt++) acc[nt] = make_float4(0.f, 0.f, 0.f, 0.f);
    gemm_core(A, rowA, rowB, vA, vB, smem, lane, acc);

#pragma unroll
    for (int nt = 0; nt < 16; nt++) {
        int col = nt * 8 + 2 * tig;
        float c0 = b1[col], c1 = b1[col + 1];
        acc[nt].x = fmaxf(acc[nt].x + c0, 0.f);
        acc[nt].y = fmaxf(acc[nt].y + c1, 0.f);
        acc[nt].z = fmaxf(acc[nt].z + c0, 0.f);
        acc[nt].w = fmaxf(acc[nt].w + c1, 0.f);
    }

    float4 acc2[16];
#pragma unroll
    for (int nt = 0; nt < 16; nt++) acc2[nt] = make_float4(0.f, 0.f, 0.f, 0.f);
    gemm_core_reg(acc, smem + WIMGSZ, lane, acc2);

    float pA0 = 0.f, pA1 = 0.f, pB0 = 0.f, pB1 = 0.f;
#pragma unroll
    for (int nt = 0; nt < 16; nt++) {
        int col = nt * 8 + 2 * tig;
        float c0 = b2v[col], c1 = b2v[col + 1];
        float rx = fmaxf(acc2[nt].x + c0, 0.f), ry = fmaxf(acc2[nt].y + c1, 0.f);
        float rz = fmaxf(acc2[nt].z + c0, 0.f), rw = fmaxf(acc2[nt].w + c1, 0.f);
        float w00 = __ldg(W2 + col * 2), w01 = __ldg(W2 + col * 2 + 1);
        float w10 = __ldg(W2 + (col + 1) * 2), w11 = __ldg(W2 + (col + 1) * 2 + 1);
        pA0 += rx * w00 + ry * w10; pA1 += rx * w01 + ry * w11;
        pB0 += rz * w00 + rw * w10; pB1 += rz * w01 + rw * w11;
    }
    pA0 += __shfl_xor_sync(0xffffffffu, pA0, 1); pA0 += __shfl_xor_sync(0xffffffffu, pA0, 2);
    pA1 += __shfl_xor_sync(0xffffffffu, pA1, 1); pA1 += __shfl_xor_sync(0xffffffffu, pA1, 2);
    pB0 += __shfl_xor_sync(0xffffffffu, pB0, 1); pB0 += __shfl_xor_sync(0xffffffffu, pB0, 2);
    pB1 += __shfl_xor_sync(0xffffffffu, pB1, 1); pB1 += __shfl_xor_sync(0xffffffffu, pB1, 2);
    if (tig == 0) {
        if (vA) { outp[(size_t)rowA * 2] = pA0 + b2[0]; outp[(size_t)rowA * 2 + 1] = pA1 + b2[1]; }
        if (vB) { outp[(size_t)rowB * 2] = pB0 + b2[0]; outp[(size_t)rowB * 2 + 1] = pB1 + b2[1]; }
    }
}

// ---------------- CSR aggregation: half-warp per edge, fused snp LN (round-10) -----
__global__ void __launch_bounds__(256) agg3(
    const float* __restrict__ ln_gp, const float* __restrict__ ln_bp,
    const float* __restrict__ fw, int layer1)
{
    int w = blockIdx.x * 8 + (threadIdx.x >> 5);
    const __half* hsrc;
    const float *ssrc, *sdst;
    const int *rp, *ss;
    float* out;
    const float* prev = nullptr;
    int d;
    bool fuse = false;
    if (w < N_GENE) {
        d = w; hsrc = g_hsh; ssrc = g_ssrc_sg; sdst = g_sdst_sg;
        rp = g_rp_sg; ss = g_ss_sg; out = g_o_sg;
    } else if (w < N_GENE + N_SNP) {
        d = w - N_GENE; hsrc = g_hgh; ssrc = g_ssrc_gs; sdst = g_sdst_gs;
        rp = g_rp_gs; ss = g_ss_gs;
        fuse = true;
        prev = layer1 ? g_out_s0 : nullptr;
        out = layer1 ? g_buf1 : g_out_s0;
    } else if (w < 2 * N_GENE + N_SNP) {
        d = w - (N_GENE + N_SNP); hsrc = g_hgh; ssrc = g_ssrc_gg; sdst = g_sdst_gg;
        rp = g_rp_gg; ss = g_ss_gg; out = g_o_gg;
    } else return;

    const int lane = threadIdx.x & 31, hw = lane >> 4, l16 = lane & 15, hd = l16 >> 1;
    float sdh = __ldg(sdst + d * 8 + hd);
    int beg = __ldg(rp + d), end = __ldg(rp + d + 1);

    float acc[8];
#pragma unroll
    for (int j = 0; j < 8; j++) acc[j] = 0.f;
    float se = 0.f;

#pragma unroll 2
    for (int i = beg; i < end; i += 2) {
        int ii = i + hw;
        if (ii < end) {
            int s = __ldg(ss + ii);
            float a = __ldg(ssrc + s * 8 + hd) + sdh;
            uint4 u = *((const uint4*)(hsrc + (size_t)s * 128) + l16);
            a = a > 0.f ? a : NEG * a;
            float e = __expf(a);
            float2 f0 = __half22float2(*(__half2*)&u.x);
            float2 f1 = __half22float2(*(__half2*)&u.y);
            float2 f2 = __half22float2(*(__half2*)&u.z);
            float2 f3 = __half22float2(*(__half2*)&u.w);
            acc[0] = fmaf(e, f0.x, acc[0]); acc[1] = fmaf(e, f0.y, acc[1]);
            acc[2] = fmaf(e, f1.x, acc[2]); acc[3] = fmaf(e, f1.y, acc[3]);
            acc[4] = fmaf(e, f2.x, acc[4]); acc[5] = fmaf(e, f2.y, acc[5]);
            acc[6] = fmaf(e, f3.x, acc[6]); acc[7] = fmaf(e, f3.y, acc[7]);
            se += e;
        }
    }
    se += __shfl_xor_sync(0xffffffffu, se, 16);
#pragma unroll
    for (int j = 0; j < 8; j++) acc[j] += __shfl_xor_sync(0xffffffffu, acc[j], 16);
    float inv = 1.f / (se + 1e-16f);
    float r[8];
#pragma unroll
    for (int j = 0; j < 8; j++) r[j] = fmaxf(acc[j] * inv, 0.f);

    if (!fuse) {
        if (hw == 0) {
            float4* op = (float4*)(out + (size_t)d * 128 + l16 * 8);
            op[0] = make_float4(r[0], r[1], r[2], r[3]);
            op[1] = make_float4(r[4], r[5], r[6], r[7]);
        }
        return;
    }

    float ps = r[0] + r[1] + r[2] + r[3] + r[4] + r[5] + r[6] + r[7];
#pragma unroll
    for (int o = 8; o; o >>= 1) ps += __shfl_xor_sync(0xffffffffu, ps, o);
    float mu = ps * (1.f / 128.f);
    float pv = 0.f;
#pragma unroll
    for (int j = 0; j < 8; j++) { float dl = r[j] - mu; pv += dl * dl; }
#pragma unroll
    for (int o = 8; o; o >>= 1) pv += __shfl_xor_sync(0xffffffffu, pv, o);
    float rs = rsqrtf(pv * (1.f / 128.f) + 1e-5f);
    if (hw == 0) {
        float4 g0 = __ldg((const float4*)ln_gp + l16 * 2);
        float4 g1 = __ldg((const float4*)ln_gp + l16 * 2 + 1);
        float4 b0 = __ldg((const float4*)ln_bp + l16 * 2);
        float4 b1 = __ldg((const float4*)ln_bp + l16 * 2 + 1);
        float4 o0, o1;
        o0.x = (r[0] - mu) * rs * g0.x + b0.x;
        o0.y = (r[1] - mu) * rs * g0.y + b0.y;
        o0.z = (r[2] - mu) * rs * g0.z + b0.z;
        o0.w = (r[3] - mu) * rs * g0.w + b0.w;
        o1.x = (r[4] - mu) * rs * g1.x + b1.x;
        o1.y = (r[5] - mu) * rs * g1.y + b1.y;
        o1.z = (r[6] - mu) * rs * g1.z + b1.z;
        o1.w = (r[7] - mu) * rs * g1.w + b1.w;
        if (prev) {
            float w0 = fw[0], w1 = fw[1];
            float iw = 1.f / (w0 + w1);
            float4 p0 = *((const float4*)(prev + (size_t)d * 128 + l16 * 8));
            float4 p1 = *((const float4*)(prev + (size_t)d * 128 + l16 * 8) + 1);
            o0.x = (w0 * p0.x + w1 * o0.x) * iw;
            o0.y = (w0 * p0.y + w1 * o0.y) * iw;
            o0.z = (w0 * p0.z + w1 * o0.z) * iw;
            o0.w = (w0 * p0.w + w1 * o0.w) * iw;
            o1.x = (w0 * p1.x + w1 * o1.x) * iw;
            o1.y = (w0 * p1.y + w1 * o1.y) * iw;
            o1.z = (w0 * p1.z + w1 * o1.z) * iw;
            o1.w = (w0 * p1.w + w1 * o1.w) * iw;
        }
        float4* op = (float4*)(out + (size_t)d * 128 + l16 * 8);
        op[0] = o0; op[1] = o1;
    }
}

// ---------------- semantic softmax (separate tiny kernel, round-10) ----------------
__global__ void sem_softmax2(const float* __restrict__ q)
{
    __shared__ float sw[8];
    int m = threadIdx.x >> 7, col = threadIdx.x & 127;
    float s = 0.f;
    const float* part = g_sempart + (size_t)m * TG_BLKS * 128 + col;
    for (int b = 0; b < TG_BLKS; b++) s += part[b * 128];
    float v = q[col] * (s / 20000.f);
    int lane = threadIdx.x & 31;
#pragma unroll
    for (int o = 16; o; o >>= 1) v += __shfl_xor_sync(0xffffffffu, v, o);
    if (lane == 0) sw[threadIdx.x >> 5] = v;
    __syncthreads();
    if (threadIdx.x == 0) {
        float s0 = sw[0] + sw[1] + sw[2] + sw[3];
        float s1 = sw[4] + sw[5] + sw[6] + sw[7];
        float mx = fmaxf(s0, s1);
        float e0 = __expf(s0 - mx), e1 = __expf(s1 - mx);
        float inv = 1.f / (e0 + e1);
        g_attn[0] = e0 * inv; g_attn[1] = e1 * inv;
    }
}

// ---------------- gene combine + LayerNorm (+ layer fusion), round-10 --------------
__global__ void __launch_bounds__(256) combine_all(
    const float* __restrict__ ln_gp, const float* __restrict__ ln_bp,
    const float* __restrict__ fw, int layer1)
{
    int idx = blockIdx.x * blockDim.x + threadIdx.x;
    int n = idx >> 5, lane = idx & 31;
    if (n >= N_GENE) return;
    const float* prev = layer1 ? g_out_g0 : nullptr;
    float* out = layer1 ? (g_buf1 + (size_t)N_SNP * 128) : g_out_g0;
    float4 v = *((const float4*)(g_o_sg + (size_t)n * 128) + lane);
    {
        float a0 = g_attn[0], a1 = g_attn[1];
        float4 u = *((const float4*)(g_o_gg + (size_t)n * 128) + lane);
        v.x = a0 * v.x + a1 * u.x;
        v.y = a0 * v.y + a1 * u.y;
        v.z = a0 * v.z + a1 * u.z;
        v.w = a0 * v.w + a1 * u.w;
    }
    float s = v.x + v.y + v.z + v.w;
#pragma unroll
    for (int o = 16; o; o >>= 1) s += __shfl_xor_sync(0xffffffffu, s, o);
    float mu = s * (1.f / 128.f);
    float dx = v.x - mu, dy = v.y - mu, dz = v.z - mu, dw = v.w - mu;
    float qv = dx * dx + dy * dy + dz * dz + dw * dw;
#pragma unroll
    for (int o = 16; o; o >>= 1) qv += __shfl_xor_sync(0xffffffffu, qv, o);
    float rs = rsqrtf(qv * (1.f / 128.f) + 1e-5f);
    float4 g4 = *((const float4*)ln_gp + lane);
    float4 b4 = *((const float4*)ln_bp + lane);
    float4 r;
    r.x = dx * rs * g4.x + b4.x;
    r.y = dy * rs * g4.y + b4.y;
    r.z = dz * rs * g4.z + b4.z;
    r.w = dw * rs * g4.w + b4.w;
    if (prev) {
        float w0 = fw[0], w1 = fw[1];
        float inv = 1.f / (w0 + w1);
        float4 p = *((const float4*)(prev + (size_t)n * 128) + lane);
        r.x = (w0 * p.x + w1 * r.x) * inv;
        r.y = (w0 * p.y + w1 * r.y) * inv;
        r.z = (w0 * p.z + w1 * r.z) * inv;
        r.w = (w0 * p.w + w1 * r.w) * inv;
    }
    *((float4*)(out + (size_t)n * 128) + lane) = r;
}

static inline int cdiv(long a, int b) { return (int)((a + b - 1) / b); }

extern "C" void kernel_launch(void* const* d_in, const int* in_sizes, int n_in,
                              void* d_out, int out_size)
{
    const float* x_snp  = (const float*)d_in[0];
    const float* x_gene = (const float*)d_in[1];
    const float* Wp_snp = (const float*)d_in[2];
    const float* bp_snp = (const float*)d_in[3];
    const float* Wp_gene= (const float*)d_in[4];
    const float* bp_gene= (const float*)d_in[5];
    const float* a_src  = (const float*)d_in[6];
    const float* a_dst  = (const float*)d_in[7];
    const float* Wk     = (const float*)d_in[8];
    const float* bk     = (const float*)d_in[9];
    const float* qvp    = (const float*)d_in[10];
    const float* ln_g   = (const float*)d_in[11];
    const float* ln_b   = (const float*)d_in[12];
    const float* fw     = (const float*)d_in[13];
    const float* Wfp    = (const float*)d_in[14];
    const float* bfp    = (const float*)d_in[15];
    const float* Wo1    = (const float*)d_in[16];
    const float* bo1    = (const float*)d_in[17];
    const float* Wo2    = (const float*)d_in[18];
    const float* bo2    = (const float*)d_in[19];
    const int* sg_s = (const int*)d_in[20];
    const int* sg_d = (const int*)d_in[21];
    const int* gs_s = (const int*)d_in[22];
    const int* gs_d = (const int*)d_in[23];
    const int* gg_s = (const int*)d_in[24];
    const int* gg_d = (const int*)d_in[25];
    const int E_sg = in_sizes[20], E_gs = in_sizes[22], E_gg = in_sizes[24];

    float *out_s0, *out_g0, *buf1;
    unsigned char* wimg;
    cudaGetSymbolAddress((void**)&out_s0, g_out_s0);
    cudaGetSymbolAddress((void**)&out_g0, g_out_g0);
    cudaGetSymbolAddress((void**)&buf1, g_buf1);
    cudaGetSymbolAddress((void**)&wimg, g_wimg);

    cudaFuncSetAttribute(proj_h, cudaFuncAttributeMaxDynamicSharedMemorySize, TG_SMEM1);
    cudaFuncSetAttribute(tgemm_sem, cudaFuncAttributeMaxDynamicSharedMemorySize, TG_SMEM_SEM);
    cudaFuncSetAttribute(final2, cudaFuncAttributeMaxDynamicSharedMemorySize, TG_SMEM_FIN);

    prep_k<<<ZB + 512, 256>>>(Wp_snp, Wp_snp + 16384, Wp_gene, Wp_gene + 16384,
                              Wk, Wk + 16384, Wfp, Wo1, wimg);

    const int E_tot = E_sg + E_gs + E_gg;
    hist3<<<cdiv(E_tot, 256), 256>>>(sg_d, gs_d, gg_d, E_sg, E_gs, E_gg);
    bsum3<<<NB_TOT, 1024>>>();
    scan3<<<NB_TOT, 1024>>>();
    scatter3<<<cdiv(E_tot, 256), 256>>>(sg_s, sg_d, gs_s, gs_d, gg_s, gg_d,
                                        E_sg, E_gs, E_gg);

    const int TS = cdiv(N_SNP, 128), TG = cdiv(N_GENE, 128), TA = cdiv(N_ALL, 128);

    for (int l = 0; l < 2; ++l) {
        const float* ins = l ? out_s0 : x_snp;
        const float* ing = l ? out_g0 : x_gene;

        proj_h<<<TS + TG, 256, TG_SMEM1>>>(ins, ing,
            wimg + l * WIMGSZ, wimg + (2 + l) * WIMGSZ,
            bp_snp + l * 128, bp_gene + l * 128, a_src, a_dst, l, TS);

        agg3<<<cdiv(2 * N_GENE + N_SNP, 8), 256>>>(ln_g + l * 128, ln_b + l * 128, fw, l);

        tgemm_sem<<<2 * TG, 256, TG_SMEM_SEM>>>(wimg + (4 + l) * WIMGSZ, bk + l * 128, TG);
        sem_softmax2<<<1, 256>>>(qvp + l * 128);

        combine_all<<<cdiv((long)N_GENE * 32, 256), 256>>>(
            ln_g + l * 128, ln_b + l * 128, fw, l);
    }

    final2<<<TA, 256, TG_SMEM_FIN>>>(buf1, wimg + 6 * WIMGSZ, wimg + 7 * WIMGSZ,
                                     bfp, bo1, Wo2, bo2, (float*)d_out, N_ALL);
}

// round 13
// speedup vs baseline: 1.0617x; 1.0080x over previous
#include <cuda_runtime.h>
#include <cuda_bf16.h>
#include <cuda_fp16.h>
#include <cstdint>

#define N_SNP  100000
#define N_GENE 20000
#define N_ALL  120000
#define HID    128
#define NEG    0.2f

#define E_SG_MAX 500000
#define E_GS_MAX 500000
#define E_GG_MAX 150000

#define SEG_GS 20000
#define SEG_GG 120000
#define NSEG_TOT 140000
#define NB_SG 20
#define NB_GS 98
#define NB_GG 20
#define NB_TOT 138

#define WROW   272
#define WLO    34816
#define WIMGSZ 69632

// ---------------- device scratch ----------------
__device__ __half   g_hsh[N_SNP * HID];
__device__ __half   g_hgh[N_GENE * HID];
__device__ float    g_ssrc_sg[N_SNP * 8];
__device__ float    g_sdst_gs[N_SNP * 8];
__device__ float    g_sdst_sg[N_GENE * 8];
__device__ float    g_ssrc_gs[N_GENE * 8];
__device__ float    g_ssrc_gg[N_GENE * 8];
__device__ float    g_sdst_gg[N_GENE * 8];
__device__ float    g_o_sg[N_GENE * HID];
__device__ float    g_o_gg[N_GENE * HID];
__device__ float    g_out_s0[N_SNP * HID];
__device__ float    g_out_g0[N_GENE * HID];
__device__ float    g_sem[2 * HID];
__device__ float    g_buf1[N_ALL * HID];
__device__ __align__(16) unsigned char g_wimg[8 * WIMGSZ];
__device__ int g_rp_sg[N_GENE + 1];
__device__ int g_rp_gs[N_SNP + 1];
__device__ int g_rp_gg[N_GENE + 1];
__device__ int g_dc[2 * NSEG_TOT];
__device__ int g_bsum[NB_TOT + 4];
__device__ int g_ss_sg[E_SG_MAX];
__device__ int g_ss_gs[E_GS_MAX];
__device__ int g_ss_gg[E_GG_MAX];

__device__ __forceinline__ uint32_t pack_bf(float x, float y) {
    __nv_bfloat162 t = __floats2bfloat162_rn(x, y);
    return *(uint32_t*)&t;
}
__device__ __forceinline__ void mma_bf16(float4& c, uint32_t a0, uint32_t a1,
                                         uint32_t a2, uint32_t a3,
                                         uint32_t b0, uint32_t b1) {
    asm volatile("mma.sync.aligned.m16n8k16.row.col.f32.bf16.bf16.f32 "
                 "{%0,%1,%2,%3}, {%4,%5,%6,%7}, {%8,%9}, {%0,%1,%2,%3};"
                 : "+f"(c.x), "+f"(c.y), "+f"(c.z), "+f"(c.w)
                 : "r"(a0), "r"(a1), "r"(a2), "r"(a3), "r"(b0), "r"(b1));
}

// Core GEMM: 16-row strip pair per warp from gmem fp32 A vs smem weight image.
__device__ __forceinline__ void gemm_core(
    const float* __restrict__ A, int rowA, int rowB, bool vA, bool vB,
    const unsigned char* sm, int lane, float4 acc[16])
{
    const int g = lane >> 2, tig = lane & 3;
    const float* ArA = A + (size_t)rowA * 128;
    const float* ArB = A + (size_t)rowB * 128;
#pragma unroll
    for (int ks = 0; ks < 8; ks++) {
        const int k0 = ks * 16;
        float2 p00 = make_float2(0.f, 0.f), p01 = p00, p10 = p00, p11 = p00;
        if (vA) {
            p00 = *(const float2*)(ArA + k0 + 2 * tig);
            p01 = *(const float2*)(ArA + k0 + 2 * tig + 8);
        }
        if (vB) {
            p10 = *(const float2*)(ArB + k0 + 2 * tig);
            p11 = *(const float2*)(ArB + k0 + 2 * tig + 8);
        }
        uint32_t ah0 = pack_bf(p00.x, p00.y), ah1 = pack_bf(p10.x, p10.y);
        uint32_t ah2 = pack_bf(p01.x, p01.y), ah3 = pack_bf(p11.x, p11.y);
        __nv_bfloat162 h00 = *(__nv_bfloat162*)&ah0, h10 = *(__nv_bfloat162*)&ah1;
        __nv_bfloat162 h01 = *(__nv_bfloat162*)&ah2, h11 = *(__nv_bfloat162*)&ah3;
        uint32_t al0 = pack_bf(p00.x - __bfloat162float(h00.x), p00.y - __bfloat162float(h00.y));
        uint32_t al1 = pack_bf(p10.x - __bfloat162float(h10.x), p10.y - __bfloat162float(h10.y));
        uint32_t al2 = pack_bf(p01.x - __bfloat162float(h01.x), p01.y - __bfloat162float(h01.y));
        uint32_t al3 = pack_bf(p11.x - __bfloat162float(h11.x), p11.y - __bfloat162float(h11.y));

        const unsigned char* bh = sm + (size_t)g * WROW + (k0 + 2 * tig) * 2;
#pragma unroll
        for (int nt = 0; nt < 16; nt++) {
            uint32_t bh0 = *(const uint32_t*)(bh + nt * 8 * WROW);
            uint32_t bh1 = *(const uint32_t*)(bh + nt * 8 * WROW + 16);
            mma_bf16(acc[nt], ah0, ah1, ah2, ah3, bh0, bh1);
            mma_bf16(acc[nt], al0, al1, al2, al3, bh0, bh1);
            uint32_t bl0 = *(const uint32_t*)(bh + WLO + nt * 8 * WROW);
            uint32_t bl1 = *(const uint32_t*)(bh + WLO + nt * 8 * WROW + 16);
            mma_bf16(acc[nt], ah0, ah1, ah2, ah3, bl0, bl1);
        }
    }
}

// Second GEMM with A operand coming from register accumulators.
__device__ __forceinline__ void gemm_core_reg(
    const float4 a1[16], const unsigned char* sm, int lane, float4 acc[16])
{
    const int g = lane >> 2, tig = lane & 3;
#pragma unroll
    for (int kt = 0; kt < 8; kt++) {
        float x0 = a1[2*kt].x,   y0 = a1[2*kt].y;
        float x1 = a1[2*kt].z,   y1 = a1[2*kt].w;
        float x2 = a1[2*kt+1].x, y2 = a1[2*kt+1].y;
        float x3 = a1[2*kt+1].z, y3 = a1[2*kt+1].w;
        uint32_t ah0 = pack_bf(x0, y0), ah1 = pack_bf(x1, y1);
        uint32_t ah2 = pack_bf(x2, y2), ah3 = pack_bf(x3, y3);
        __nv_bfloat162 h0 = *(__nv_bfloat162*)&ah0, h1 = *(__nv_bfloat162*)&ah1;
        __nv_bfloat162 h2 = *(__nv_bfloat162*)&ah2, h3 = *(__nv_bfloat162*)&ah3;
        uint32_t al0 = pack_bf(x0 - __bfloat162float(h0.x), y0 - __bfloat162float(h0.y));
        uint32_t al1 = pack_bf(x1 - __bfloat162float(h1.x), y1 - __bfloat162float(h1.y));
        uint32_t al2 = pack_bf(x2 - __bfloat162float(h2.x), y2 - __bfloat162float(h2.y));
        uint32_t al3 = pack_bf(x3 - __bfloat162float(h3.x), y3 - __bfloat162float(h3.y));

        const unsigned char* bh = sm + (size_t)g * WROW + (kt * 16 + 2 * tig) * 2;
#pragma unroll
        for (int nt = 0; nt < 16; nt++) {
            uint32_t bh0 = *(const uint32_t*)(bh + nt * 8 * WROW);
            uint32_t bh1 = *(const uint32_t*)(bh + nt * 8 * WROW + 16);
            mma_bf16(acc[nt], ah0, ah1, ah2, ah3, bh0, bh1);
            mma_bf16(acc[nt], al0, al1, al2, al3, bh0, bh1);
            uint32_t bl0 = *(const uint32_t*)(bh + WLO + nt * 8 * WROW);
            uint32_t bl1 = *(const uint32_t*)(bh + WLO + nt * 8 * WROW + 16);
            mma_bf16(acc[nt], ah0, ah1, ah2, ah3, bl0, bl1);
        }
    }
}

// ---------------- prep: zero counters + weight images in ONE launch ----------------
#define ZB 1094   // cdiv(2*NSEG_TOT,256)
__global__ void prep_k(const float* __restrict__ W0, const float* __restrict__ W1,
                       const float* __restrict__ W2, const float* __restrict__ W3,
                       const float* __restrict__ W4, const float* __restrict__ W5,
                       const float* __restrict__ W6, const float* __restrict__ W7,
                       unsigned char* __restrict__ imgbase) {
    if (blockIdx.x < ZB) {
        int i = blockIdx.x * 256 + threadIdx.x;
        if (i < 2 * NSEG_TOT) g_dc[i] = 0;
        return;
    }
    int bb = blockIdx.x - ZB;
    int b = bb >> 6;
    const float* W;
    if      (b == 0) W = W0; else if (b == 1) W = W1;
    else if (b == 2) W = W2; else if (b == 3) W = W3;
    else if (b == 4) W = W4; else if (b == 5) W = W5;
    else if (b == 6) W = W6; else              W = W7;
    unsigned char* img = imgbase + (size_t)b * WIMGSZ;
    int i = (bb & 63) * 256 + threadIdx.x;
    int n = i >> 7, k = i & 127;
    float w = W[k * 128 + n];
    __nv_bfloat16 h = __float2bfloat16(w);
    __nv_bfloat16 l = __float2bfloat16(w - __bfloat162float(h));
    *(uint16_t*)(img + n * WROW + k * 2) = __bfloat16_as_ushort(h);
    *(uint16_t*)(img + WLO + n * WROW + k * 2) = __bfloat16_as_ushort(l);
}

// ---------------- CSR build ----------------
__global__ void hist3(const int* __restrict__ d1, const int* __restrict__ d2,
                      const int* __restrict__ d3, int E1, int E2, int E3) {
    int i = blockIdx.x * 256 + threadIdx.x;
    if (i < E1) atomicAdd(g_dc + d1[i], 1);
    else if (i < E1 + E2) atomicAdd(g_dc + SEG_GS + d2[i - E1], 1);
    else if (i < E1 + E2 + E3) atomicAdd(g_dc + SEG_GG + d3[i - E1 - E2], 1);
}
__device__ __forceinline__ void seg_map(int b, int& degoff, int& nd, int& boff, int& lb) {
    if (b < NB_SG)            { degoff = 0;      nd = N_GENE; boff = 0;             lb = b; }
    else if (b < NB_SG+NB_GS) { degoff = SEG_GS; nd = N_SNP;  boff = NB_SG;         lb = b - NB_SG; }
    else                      { degoff = SEG_GG; nd = N_GENE; boff = NB_SG + NB_GS; lb = b - NB_SG - NB_GS; }
}
__global__ void bsum3() {
    __shared__ int sw[32];
    int degoff, nd, boff, lb;
    seg_map(blockIdx.x, degoff, nd, boff, lb);
    int i = lb * 1024 + threadIdx.x;
    int v = (i < nd) ? g_dc[degoff + i] : 0;
#pragma unroll
    for (int o = 16; o; o >>= 1) v += __shfl_xor_sync(0xffffffffu, v, o);
    if ((threadIdx.x & 31) == 0) sw[threadIdx.x >> 5] = v;
    __syncthreads();
    if (threadIdx.x < 32) {
        int t = sw[threadIdx.x];
#pragma unroll
        for (int o = 16; o; o >>= 1) t += __shfl_xor_sync(0xffffffffu, t, o);
        if (threadIdx.x == 0) g_bsum[boff + lb] = t;
    }
}
// scan3 computes its own block base from g_bsum prefix (no bscan kernel).
__global__ void scan3() {
    __shared__ int sm[1024];
    __shared__ int sbase;
    int degoff, nd, boff, lb;
    seg_map(blockIdx.x, degoff, nd, boff, lb);
    int* rp = (blockIdx.x < NB_SG) ? g_rp_sg
            : (blockIdx.x < NB_SG + NB_GS) ? g_rp_gs : g_rp_gg;
    int tid = threadIdx.x;
    if (tid == 0) sbase = 0;
    __syncthreads();
    if (tid < lb) atomicAdd(&sbase, g_bsum[boff + tid]);
    int i = lb * 1024 + tid;
    int v = (i < nd) ? g_dc[degoff + i] : 0;
    sm[tid] = v;
    __syncthreads();
#pragma unroll
    for (int off = 1; off < 1024; off <<= 1) {
        int t = (tid >= off) ? sm[tid - off] : 0;
        __syncthreads();
        sm[tid] += t;
        __syncthreads();
    }
    int incl = sm[tid];
    int base = sbase;
    if (i < nd) rp[i] = base + incl - v;
    if (i == nd - 1) rp[nd] = base + incl;
}
__global__ void scatter3(const int* __restrict__ s1, const int* __restrict__ d1,
                         const int* __restrict__ s2, const int* __restrict__ d2,
                         const int* __restrict__ s3, const int* __restrict__ d3,
                         int E1, int E2, int E3) {
    int i = blockIdx.x * 256 + threadIdx.x;
    if (i < E1) {
        int d = d1[i];
        g_ss_sg[g_rp_sg[d] + atomicAdd(g_dc + NSEG_TOT + d, 1)] = s1[i];
    } else if (i < E1 + E2) {
        int e = i - E1, d = d2[e];
        g_ss_gs[g_rp_gs[d] + atomicAdd(g_dc + NSEG_TOT + SEG_GS + d, 1)] = s2[e];
    } else if (i < E1 + E2 + E3) {
        int e = i - E1 - E2, d = d3[e];
        g_ss_gg[g_rp_gg[d] + atomicAdd(g_dc + NSEG_TOT + SEG_GG + d, 1)] = s3[e];
    }
}

// ---------------- merged projection GEMM: snp + gene in one launch ----------------
#define TG_SMEM1 (WIMGSZ + 16)

__global__ void __launch_bounds__(256) proj_h(
    const float* __restrict__ As, const float* __restrict__ Ag,
    const unsigned char* __restrict__ imgS, const unsigned char* __restrict__ imgG,
    const float* __restrict__ bS, const float* __restrict__ bG,
    const float* __restrict__ a_src, const float* __restrict__ a_dst,
    int l, int nsblk)
{
    extern __shared__ unsigned char smem[];
    const int tid = threadIdx.x, wid = tid >> 5, lane = tid & 31;
    const int g = lane >> 2, tig = lane & 3;
    const bool is_snp = blockIdx.x < nsblk;
    const int blk = is_snp ? blockIdx.x : blockIdx.x - nsblk;
    const float* A = is_snp ? As : Ag;
    const unsigned char* Bimg = is_snp ? imgS : imgG;
    const float* bias = is_snp ? bS : bG;
    const int M = is_snp ? N_SNP : N_GENE;
    __half* Ch = is_snp ? g_hsh : g_hgh;

    {
        const uint4* src = (const uint4*)Bimg;
        uint4* dst = (uint4*)smem;
#pragma unroll
        for (int i = 0; i < 17; i++) {
            int idx = tid + 256 * i;
            if (idx < WIMGSZ / 16) dst[idx] = src[idx];
        }
    }
    __syncthreads();

    const int rowA = blk * 128 + wid * 16 + g;
    const int rowB = rowA + 8;
    const bool vA = rowA < M, vB = rowB < M;

    float4 acc[16];
#pragma unroll
    for (int nt = 0; nt < 16; nt++) acc[nt] = make_float4(0.f, 0.f, 0.f, 0.f);
    gemm_core(A, rowA, rowB, vA, vB, smem, lane, acc);

#pragma unroll
    for (int nt = 0; nt < 16; nt++) {
        int col = nt * 8 + 2 * tig;
        float b0 = bias[col], b1 = bias[col + 1];
        acc[nt].x += b0; acc[nt].y += b1;
        acc[nt].z += b0; acc[nt].w += b1;
    }

#pragma unroll
    for (int nt = 0; nt < 16; nt++) {
        int col = nt * 8 + 2 * tig;
        if (vA) *((__half2*)(Ch + (size_t)rowA * 128 + col)) = __floats2half2_rn(acc[nt].x, acc[nt].y);
        if (vB) *((__half2*)(Ch + (size_t)rowB * 128 + col)) = __floats2half2_rn(acc[nt].z, acc[nt].w);
    }

    const float* vv[4];
    float* sb[4];
    int nv;
    if (is_snp) {
        nv = 2;
        vv[0] = a_src + (l * 3 + 0) * 128; sb[0] = g_ssrc_sg;
        vv[1] = a_dst + (l * 3 + 1) * 128; sb[1] = g_sdst_gs;
        vv[2] = nullptr; vv[3] = nullptr;
    } else {
        nv = 4;
        vv[0] = a_dst + (l * 3 + 0) * 128; sb[0] = g_sdst_sg;
        vv[1] = a_src + (l * 3 + 1) * 128; sb[1] = g_ssrc_gs;
        vv[2] = a_src + (l * 3 + 2) * 128; sb[2] = g_ssrc_gg;
        vv[3] = a_dst + (l * 3 + 2) * 128; sb[3] = g_sdst_gg;
    }
#pragma unroll
    for (int v = 0; v < 4; v++) {
        if (v < nv) {
#pragma unroll
            for (int hd = 0; hd < 8; hd++) {
                float a0 = __ldg(vv[v] + 16 * hd + 2 * tig);
                float a1 = __ldg(vv[v] + 16 * hd + 2 * tig + 1);
                float a2 = __ldg(vv[v] + 16 * hd + 8 + 2 * tig);
                float a3 = __ldg(vv[v] + 16 * hd + 8 + 2 * tig + 1);
                float pA = acc[2*hd].x * a0 + acc[2*hd].y * a1
                         + acc[2*hd+1].x * a2 + acc[2*hd+1].y * a3;
                float pB = acc[2*hd].z * a0 + acc[2*hd].w * a1
                         + acc[2*hd+1].z * a2 + acc[2*hd+1].w * a3;
                pA += __shfl_xor_sync(0xffffffffu, pA, 1);
                pA += __shfl_xor_sync(0xffffffffu, pA, 2);
                pB += __shfl_xor_sync(0xffffffffu, pB, 1);
                pB += __shfl_xor_sync(0xffffffffu, pB, 2);
                if (tig == 0) {
                    if (vA) sb[v][rowA * 8 + hd] = pA;
                    if (vB) sb[v][rowB * 8 + hd] = pB;
                }
            }
        }
    }
}

// ---------------- semantic GEMM: tanh colsums accumulated atomically into g_sem ----
#define TG_SMEM_SEM (WIMGSZ + 512)

__global__ void __launch_bounds__(256) tgemm_sem(
    const unsigned char* __restrict__ Bimg, const float* __restrict__ bias, int nhalf)
{
    extern __shared__ unsigned char smem[];
    float* scs = (float*)(smem + WIMGSZ);
    const int tid = threadIdx.x, wid = tid >> 5, lane = tid & 31;
    const int g = lane >> 2, tig = lane & 3;
    int blk = blockIdx.x;
    const float* A = g_o_sg;
    int msel = 0;
    if (blk >= nhalf) { A = g_o_gg; blk -= nhalf; msel = 1; }

    {
        const uint4* src = (const uint4*)Bimg;
        uint4* dst = (uint4*)smem;
#pragma unroll
        for (int i = 0; i < 17; i++) {
            int idx = tid + 256 * i;
            if (idx < WIMGSZ / 16) dst[idx] = src[idx];
        }
    }
    if (tid < 128) scs[tid] = 0.f;
    __syncthreads();

    const int rowA = blk * 128 + wid * 16 + g;
    const int rowB = rowA + 8;
    const bool vA = rowA < N_GENE, vB = rowB < N_GENE;

    float4 acc[16];
#pragma unroll
    for (int nt = 0; nt < 16; nt++) acc[nt] = make_float4(0.f, 0.f, 0.f, 0.f);
    gemm_core(A, rowA, rowB, vA, vB, smem, lane, acc);

#pragma unroll
    for (int nt = 0; nt < 16; nt++) {
        int col = nt * 8 + 2 * tig;
        float b0 = bias[col], b1 = bias[col + 1];
        float s0 = 0.f, s1 = 0.f;
        if (vA) { s0 += tanhf(acc[nt].x + b0); s1 += tanhf(acc[nt].y + b1); }
        if (vB) { s0 += tanhf(acc[nt].z + b0); s1 += tanhf(acc[nt].w + b1); }
        atomicAdd(scs + col, s0);
        atomicAdd(scs + col + 1, s1);
    }
    __syncthreads();
    if (tid < 128) atomicAdd(g_sem + msel * 128 + tid, scs[tid]);
}

// ---------------- final fused MLP (4 row-tiles per CTA) ----------------
#define TG_SMEM_FIN (2 * WIMGSZ)
#define FIN_TPB 4

__global__ void __launch_bounds__(256) final2(
    const float* __restrict__ A,
    const unsigned char* __restrict__ img1, const unsigned char* __restrict__ img2,
    const float* __restrict__ b1, const float* __restrict__ b2v,
    const float* __restrict__ W2, const float* __restrict__ b2,
    float* __restrict__ outp, int M)
{
    extern __shared__ unsigned char smem[];
    const int tid = threadIdx.x, wid = tid >> 5, lane = tid & 31;
    const int g = lane >> 2, tig = lane & 3;

    {
        const uint4* s1 = (const uint4*)img1;
        const uint4* s2 = (const uint4*)img2;
        uint4* d1 = (uint4*)smem;
        uint4* d2 = (uint4*)(smem + WIMGSZ);
#pragma unroll
        for (int i = 0; i < 17; i++) {
            int idx = tid + 256 * i;
            if (idx < WIMGSZ / 16) { d1[idx] = s1[idx]; d2[idx] = s2[idx]; }
        }
    }
    __syncthreads();

    for (int t = 0; t < FIN_TPB; t++) {
        const int rowA = (blockIdx.x * FIN_TPB + t) * 128 + wid * 16 + g;
        const int rowB = rowA + 8;
        const bool vA = rowA < M, vB = rowB < M;
        if (!vA && !vB) break;

        float4 acc[16];
#pragma unroll
        for (int nt = 0; nt < 16; nt++) acc[nt] = make_float4(0.f, 0.f, 0.f, 0.f);
        gemm_core(A, rowA, rowB, vA, vB, smem, lane, acc);

#pragma unroll
        for (int nt = 0; nt < 16; nt++) {
            int col = nt * 8 + 2 * tig;
            float c0 = b1[col], c1 = b1[col + 1];
            acc[nt].x = fmaxf(acc[nt].x + c0, 0.f);
            acc[nt].y = fmaxf(acc[nt].y + c1, 0.f);
            acc[nt].z = fmaxf(acc[nt].z + c0, 0.f);
            acc[nt].w = fmaxf(acc[nt].w + c1, 0.f);
        }

        float4 acc2[16];
#pragma unroll
        for (int nt = 0; nt < 16; nt++) acc2[nt] = make_float4(0.f, 0.f, 0.f, 0.f);
        gemm_core_reg(acc, smem + WIMGSZ, lane, acc2);

        float pA0 = 0.f, pA1 = 0.f, pB0 = 0.f, pB1 = 0.f;
#pragma unroll
        for (int nt = 0; nt < 16; nt++) {
            int col = nt * 8 + 2 * tig;
            float c0 = b2v[col], c1 = b2v[col + 1];
            float rx = fmaxf(acc2[nt].x + c0, 0.f), ry = fmaxf(acc2[nt].y + c1, 0.f);
            float rz = fmaxf(acc2[nt].z + c0, 0.f), rw = fmaxf(acc2[nt].w + c1, 0.f);
            float w00 = __ldg(W2 + col * 2), w01 = __ldg(W2 + col * 2 + 1);
            float w10 = __ldg(W2 + (col + 1) * 2), w11 = __ldg(W2 + (col + 1) * 2 + 1);
            pA0 += rx * w00 + ry * w10; pA1 += rx * w01 + ry * w11;
            pB0 += rz * w00 + rw * w10; pB1 += rz * w01 + rw * w11;
        }
        pA0 += __shfl_xor_sync(0xffffffffu, pA0, 1); pA0 += __shfl_xor_sync(0xffffffffu, pA0, 2);
        pA1 += __shfl_xor_sync(0xffffffffu, pA1, 1); pA1 += __shfl_xor_sync(0xffffffffu, pA1, 2);
        pB0 += __shfl_xor_sync(0xffffffffu, pB0, 1); pB0 += __shfl_xor_sync(0xffffffffu, pB0, 2);
        pB1 += __shfl_xor_sync(0xffffffffu, pB1, 1); pB1 += __shfl_xor_sync(0xffffffffu, pB1, 2);
        if (tig == 0) {
            if (vA) { outp[(size_t)rowA * 2] = pA0 + b2[0]; outp[(size_t)rowA * 2 + 1] = pA1 + b2[1]; }
            if (vB) { outp[(size_t)rowB * 2] = pB0 + b2[0]; outp[(size_t)rowB * 2 + 1] = pB1 + b2[1]; }
        }
    }
}

// ---------------- CSR aggregation: half-warp per edge, fused snp LN ----------------
// block 0 additionally zeroes g_sem for the following tgemm_sem accumulation.
__global__ void __launch_bounds__(256) agg3(
    const float* __restrict__ ln_gp, const float* __restrict__ ln_bp,
    const float* __restrict__ fw, int layer1)
{
    if (blockIdx.x == 0) g_sem[threadIdx.x] = 0.f;

    int w = blockIdx.x * 8 + (threadIdx.x >> 5);
    const __half* hsrc;
    const float *ssrc, *sdst;
    const int *rp, *ss;
    float* out;
    const float* prev = nullptr;
    int d;
    bool fuse = false;
    if (w < N_GENE) {
        d = w; hsrc = g_hsh; ssrc = g_ssrc_sg; sdst = g_sdst_sg;
        rp = g_rp_sg; ss = g_ss_sg; out = g_o_sg;
    } else if (w < N_GENE + N_SNP) {
        d = w - N_GENE; hsrc = g_hgh; ssrc = g_ssrc_gs; sdst = g_sdst_gs;
        rp = g_rp_gs; ss = g_ss_gs;
        fuse = true;
        prev = layer1 ? g_out_s0 : nullptr;
        out = layer1 ? g_buf1 : g_out_s0;
    } else if (w < 2 * N_GENE + N_SNP) {
        d = w - (N_GENE + N_SNP); hsrc = g_hgh; ssrc = g_ssrc_gg; sdst = g_sdst_gg;
        rp = g_rp_gg; ss = g_ss_gg; out = g_o_gg;
    } else return;

    const int lane = threadIdx.x & 31, hw = lane >> 4, l16 = lane & 15, hd = l16 >> 1;
    float sdh = __ldg(sdst + d * 8 + hd);
    int beg = __ldg(rp + d), end = __ldg(rp + d + 1);

    float acc[8];
#pragma unroll
    for (int j = 0; j < 8; j++) acc[j] = 0.f;
    float se = 0.f;

#pragma unroll 2
    for (int i = beg; i < end; i += 2) {
        int ii = i + hw;
        if (ii < end) {
            int s = __ldg(ss + ii);
            float a = __ldg(ssrc + s * 8 + hd) + sdh;
            uint4 u = *((const uint4*)(hsrc + (size_t)s * 128) + l16);
            a = a > 0.f ? a : NEG * a;
            float e = __expf(a);
            float2 f0 = __half22float2(*(__half2*)&u.x);
            float2 f1 = __half22float2(*(__half2*)&u.y);
            float2 f2 = __half22float2(*(__half2*)&u.z);
            float2 f3 = __half22float2(*(__half2*)&u.w);
            acc[0] = fmaf(e, f0.x, acc[0]); acc[1] = fmaf(e, f0.y, acc[1]);
            acc[2] = fmaf(e, f1.x, acc[2]); acc[3] = fmaf(e, f1.y, acc[3]);
            acc[4] = fmaf(e, f2.x, acc[4]); acc[5] = fmaf(e, f2.y, acc[5]);
            acc[6] = fmaf(e, f3.x, acc[6]); acc[7] = fmaf(e, f3.y, acc[7]);
            se += e;
        }
    }
    se += __shfl_xor_sync(0xffffffffu, se, 16);
#pragma unroll
    for (int j = 0; j < 8; j++) acc[j] += __shfl_xor_sync(0xffffffffu, acc[j], 16);
    float inv = 1.f / (se + 1e-16f);
    float r[8];
#pragma unroll
    for (int j = 0; j < 8; j++) r[j] = fmaxf(acc[j] * inv, 0.f);

    if (!fuse) {
        if (hw == 0) {
            float4* op = (float4*)(out + (size_t)d * 128 + l16 * 8);
            op[0] = make_float4(r[0], r[1], r[2], r[3]);
            op[1] = make_float4(r[4], r[5], r[6], r[7]);
        }
        return;
    }

    float ps = r[0] + r[1] + r[2] + r[3] + r[4] + r[5] + r[6] + r[7];
#pragma unroll
    for (int o = 8; o; o >>= 1) ps += __shfl_xor_sync(0xffffffffu, ps, o);
    float mu = ps * (1.f / 128.f);
    float pv = 0.f;
#pragma unroll
    for (int j = 0; j < 8; j++) { float dl = r[j] - mu; pv += dl * dl; }
#pragma unroll
    for (int o = 8; o; o >>= 1) pv += __shfl_xor_sync(0xffffffffu, pv, o);
    float rs = rsqrtf(pv * (1.f / 128.f) + 1e-5f);
    if (hw == 0) {
        float4 g0 = __ldg((const float4*)ln_gp + l16 * 2);
        float4 g1 = __ldg((const float4*)ln_gp + l16 * 2 + 1);
        float4 b0 = __ldg((const float4*)ln_bp + l16 * 2);
        float4 b1 = __ldg((const float4*)ln_bp + l16 * 2 + 1);
        float4 o0, o1;
        o0.x = (r[0] - mu) * rs * g0.x + b0.x;
        o0.y = (r[1] - mu) * rs * g0.y + b0.y;
        o0.z = (r[2] - mu) * rs * g0.z + b0.z;
        o0.w = (r[3] - mu) * rs * g0.w + b0.w;
        o1.x = (r[4] - mu) * rs * g1.x + b1.x;
        o1.y = (r[5] - mu) * rs * g1.y + b1.y;
        o1.z = (r[6] - mu) * rs * g1.z + b1.z;
        o1.w = (r[7] - mu) * rs * g1.w + b1.w;
        if (prev) {
            float w0 = fw[0], w1 = fw[1];
            float iw = 1.f / (w0 + w1);
            float4 p0 = *((const float4*)(prev + (size_t)d * 128 + l16 * 8));
            float4 p1 = *((const float4*)(prev + (size_t)d * 128 + l16 * 8) + 1);
            o0.x = (w0 * p0.x + w1 * o0.x) * iw;
            o0.y = (w0 * p0.y + w1 * o0.y) * iw;
            o0.z = (w0 * p0.z + w1 * o0.z) * iw;
            o0.w = (w0 * p0.w + w1 * o0.w) * iw;
            o1.x = (w0 * p1.x + w1 * o1.x) * iw;
            o1.y = (w0 * p1.y + w1 * o1.y) * iw;
            o1.z = (w0 * p1.z + w1 * o1.z) * iw;
            o1.w = (w0 * p1.w + w1 * o1.w) * iw;
        }
        float4* op = (float4*)(out + (size_t)d * 128 + l16 * 8);
        op[0] = o0; op[1] = o1;
    }
}

// ---------------- gene combine + inline cheap semantic softmax + LayerNorm ----------
__global__ void __launch_bounds__(256) combine_all(
    const float* __restrict__ q,
    const float* __restrict__ ln_gp, const float* __restrict__ ln_bp,
    const float* __restrict__ fw, int layer1)
{
    __shared__ float sw[8];
    __shared__ float sattn[2];
    const int tid = threadIdx.x, wid = tid >> 5, lane = tid & 31;

    // cheap inline softmax from the 256-float accumulated buffer
    {
        int col = tid & 127;
        float v = __ldg(q + col) * (g_sem[tid] / 20000.f);
#pragma unroll
        for (int o = 16; o; o >>= 1) v += __shfl_xor_sync(0xffffffffu, v, o);
        if (lane == 0) sw[wid] = v;
        __syncthreads();
        if (tid == 0) {
            float s0 = sw[0] + sw[1] + sw[2] + sw[3];
            float s1 = sw[4] + sw[5] + sw[6] + sw[7];
            float mx = fmaxf(s0, s1);
            float e0 = __expf(s0 - mx), e1 = __expf(s1 - mx);
            float iv = 1.f / (e0 + e1);
            sattn[0] = e0 * iv; sattn[1] = e1 * iv;
        }
        __syncthreads();
    }
    const float a0 = sattn[0], a1 = sattn[1];

    int n = (blockIdx.x * 256 + tid) >> 5;
    if (n >= N_GENE) return;
    const float* prev = layer1 ? g_out_g0 : nullptr;
    float* out = layer1 ? (g_buf1 + (size_t)N_SNP * 128) : g_out_g0;
    float4 v = *((const float4*)(g_o_sg + (size_t)n * 128) + lane);
    {
        float4 u = *((const float4*)(g_o_gg + (size_t)n * 128) + lane);
        v.x = a0 * v.x + a1 * u.x;
        v.y = a0 * v.y + a1 * u.y;
        v.z = a0 * v.z + a1 * u.z;
        v.w = a0 * v.w + a1 * u.w;
    }
    float s = v.x + v.y + v.z + v.w;
#pragma unroll
    for (int o = 16; o; o >>= 1) s += __shfl_xor_sync(0xffffffffu, s, o);
    float mu = s * (1.f / 128.f);
    float dx = v.x - mu, dy = v.y - mu, dz = v.z - mu, dw = v.w - mu;
    float qv = dx * dx + dy * dy + dz * dz + dw * dw;
#pragma unroll
    for (int o = 16; o; o >>= 1) qv += __shfl_xor_sync(0xffffffffu, qv, o);
    float rs = rsqrtf(qv * (1.f / 128.f) + 1e-5f);
    float4 g4 = *((const float4*)ln_gp + lane);
    float4 b4 = *((const float4*)ln_bp + lane);
    float4 r;
    r.x = dx * rs * g4.x + b4.x;
    r.y = dy * rs * g4.y + b4.y;
    r.z = dz * rs * g4.z + b4.z;
    r.w = dw * rs * g4.w + b4.w;
    if (prev) {
        float w0 = fw[0], w1 = fw[1];
        float inv = 1.f / (w0 + w1);
        float4 p = *((const float4*)(prev + (size_t)n * 128) + lane);
        r.x = (w0 * p.x + w1 * r.x) * inv;
        r.y = (w0 * p.y + w1 * r.y) * inv;
        r.z = (w0 * p.z + w1 * r.z) * inv;
        r.w = (w0 * p.w + w1 * r.w) * inv;
    }
    *((float4*)(out + (size_t)n * 128) + lane) = r;
}

static inline int cdiv(long a, int b) { return (int)((a + b - 1) / b); }

extern "C" void kernel_launch(void* const* d_in, const int* in_sizes, int n_in,
                              void* d_out, int out_size)
{
    const float* x_snp  = (const float*)d_in[0];
    const float* x_gene = (const float*)d_in[1];
    const float* Wp_snp = (const float*)d_in[2];
    const float* bp_snp = (const float*)d_in[3];
    const float* Wp_gene= (const float*)d_in[4];
    const float* bp_gene= (const float*)d_in[5];
    const float* a_src  = (const float*)d_in[6];
    const float* a_dst  = (const float*)d_in[7];
    const float* Wk     = (const float*)d_in[8];
    const float* bk     = (const float*)d_in[9];
    const float* qvp    = (const float*)d_in[10];
    const float* ln_g   = (const float*)d_in[11];
    const float* ln_b   = (const float*)d_in[12];
    const float* fw     = (const float*)d_in[13];
    const float* Wfp    = (const float*)d_in[14];
    const float* bfp    = (const float*)d_in[15];
    const float* Wo1    = (const float*)d_in[16];
    const float* bo1    = (const float*)d_in[17];
    const float* Wo2    = (const float*)d_in[18];
    const float* bo2    = (const float*)d_in[19];
    const int* sg_s = (const int*)d_in[20];
    const int* sg_d = (const int*)d_in[21];
    const int* gs_s = (const int*)d_in[22];
    const int* gs_d = (const int*)d_in[23];
    const int* gg_s = (const int*)d_in[24];
    const int* gg_d = (const int*)d_in[25];
    const int E_sg = in_sizes[20], E_gs = in_sizes[22], E_gg = in_sizes[24];

    float *out_s0, *out_g0, *buf1;
    unsigned char* wimg;
    cudaGetSymbolAddress((void**)&out_s0, g_out_s0);
    cudaGetSymbolAddress((void**)&out_g0, g_out_g0);
    cudaGetSymbolAddress((void**)&buf1, g_buf1);
    cudaGetSymbolAddress((void**)&wimg, g_wimg);

    cudaFuncSetAttribute(proj_h, cudaFuncAttributeMaxDynamicSharedMemorySize, TG_SMEM1);
    cudaFuncSetAttribute(tgemm_sem, cudaFuncAttributeMaxDynamicSharedMemorySize, TG_SMEM_SEM);
    cudaFuncSetAttribute(final2, cudaFuncAttributeMaxDynamicSharedMemorySize, TG_SMEM_FIN);

    prep_k<<<ZB + 512, 256>>>(Wp_snp, Wp_snp + 16384, Wp_gene, Wp_gene + 16384,
                              Wk, Wk + 16384, Wfp, Wo1, wimg);

    const int E_tot = E_sg + E_gs + E_gg;
    hist3<<<cdiv(E_tot, 256), 256>>>(sg_d, gs_d, gg_d, E_sg, E_gs, E_gg);
    bsum3<<<NB_TOT, 1024>>>();
    scan3<<<NB_TOT, 1024>>>();
    scatter3<<<cdiv(E_tot, 256), 256>>>(sg_s, sg_d, gs_s, gs_d, gg_s, gg_d,
                                        E_sg, E_gs, E_gg);

    const int TS = cdiv(N_SNP, 128), TG = cdiv(N_GENE, 128), TA = cdiv(N_ALL, 128);

    for (int l = 0; l < 2; ++l) {
        const float* ins = l ? out_s0 : x_snp;
        const float* ing = l ? out_g0 : x_gene;

        proj_h<<<TS + TG, 256, TG_SMEM1>>>(ins, ing,
            wimg + l * WIMGSZ, wimg + (2 + l) * WIMGSZ,
            bp_snp + l * 128, bp_gene + l * 128, a_src, a_dst, l, TS);

        agg3<<<cdiv(2 * N_GENE + N_SNP, 8), 256>>>(ln_g + l * 128, ln_b + l * 128, fw, l);

        tgemm_sem<<<2 * TG, 256, TG_SMEM_SEM>>>(wimg + (4 + l) * WIMGSZ, bk + l * 128, TG);

        combine_all<<<cdiv((long)N_GENE * 32, 256), 256>>>(qvp + l * 128,
            ln_g + l * 128, ln_b + l * 128, fw, l);
    }

    final2<<<cdiv(TA, FIN_TPB), 256, TG_SMEM_FIN>>>(buf1, wimg + 6 * WIMGSZ, wimg + 7 * WIMGSZ,
                                                    bfp, bo1, Wo2, bo2, (float*)d_out, N_ALL);
}

// round 14
// speedup vs baseline: 1.1646x; 1.0969x over previous
#include <cuda_runtime.h>
#include <cuda_bf16.h>
#include <cuda_fp16.h>
#include <cstdint>

#define N_SNP  100000
#define N_GENE 20000
#define N_ALL  120000
#define HID    128
#define NEG    0.2f

#define E_SG_MAX 500000
#define E_GS_MAX 500000
#define E_GG_MAX 150000

#define SEG_GS 20000
#define SEG_GG 120000
#define NSEG_TOT 140000
#define NB_SG 20
#define NB_GS 98
#define NB_GG 20
#define NB_TOT 138

#define WROW   272
#define WLO    34816
#define WIMGSZ 69632

// ---------------- device scratch ----------------
__device__ __half   g_hsh[N_SNP * HID];
__device__ __half   g_hgh[N_GENE * HID];
__device__ float    g_ssrc_sg[N_SNP * 8];
__device__ float    g_sdst_gs[N_SNP * 8];
__device__ float    g_sdst_sg[N_GENE * 8];
__device__ float    g_ssrc_gs[N_GENE * 8];
__device__ float    g_ssrc_gg[N_GENE * 8];
__device__ float    g_sdst_gg[N_GENE * 8];
__device__ float    g_o_sg[N_GENE * HID];
__device__ float    g_o_gg[N_GENE * HID];
__device__ float    g_out_s0[N_SNP * HID];
__device__ float    g_out_g0[N_GENE * HID];
__device__ float    g_sem[2 * HID];
__device__ float    g_buf1[N_ALL * HID];
__device__ __align__(16) unsigned char g_wimg[8 * WIMGSZ];
__device__ int g_rp_sg[N_GENE + 1];
__device__ int g_rp_gs[N_SNP + 1];
__device__ int g_rp_gg[N_GENE + 1];
__device__ int g_dc[2 * NSEG_TOT];
__device__ int g_bsum[NB_TOT + 4];
__device__ int g_ss_sg[E_SG_MAX];
__device__ int g_ss_gs[E_GS_MAX];
__device__ int g_ss_gg[E_GG_MAX];

__device__ __forceinline__ uint32_t pack_bf(float x, float y) {
    __nv_bfloat162 t = __floats2bfloat162_rn(x, y);
    return *(uint32_t*)&t;
}
__device__ __forceinline__ void mma_bf16(float4& c, uint32_t a0, uint32_t a1,
                                         uint32_t a2, uint32_t a3,
                                         uint32_t b0, uint32_t b1) {
    asm volatile("mma.sync.aligned.m16n8k16.row.col.f32.bf16.bf16.f32 "
                 "{%0,%1,%2,%3}, {%4,%5,%6,%7}, {%8,%9}, {%0,%1,%2,%3};"
                 : "+f"(c.x), "+f"(c.y), "+f"(c.z), "+f"(c.w)
                 : "r"(a0), "r"(a1), "r"(a2), "r"(a3), "r"(b0), "r"(b1));
}

// Core GEMM: 16-row strip pair per warp from gmem fp32 A vs smem weight image.
__device__ __forceinline__ void gemm_core(
    const float* __restrict__ A, int rowA, int rowB, bool vA, bool vB,
    const unsigned char* sm, int lane, float4 acc[16])
{
    const int g = lane >> 2, tig = lane & 3;
    const float* ArA = A + (size_t)rowA * 128;
    const float* ArB = A + (size_t)rowB * 128;
#pragma unroll
    for (int ks = 0; ks < 8; ks++) {
        const int k0 = ks * 16;
        float2 p00 = make_float2(0.f, 0.f), p01 = p00, p10 = p00, p11 = p00;
        if (vA) {
            p00 = *(const float2*)(ArA + k0 + 2 * tig);
            p01 = *(const float2*)(ArA + k0 + 2 * tig + 8);
        }
        if (vB) {
            p10 = *(const float2*)(ArB + k0 + 2 * tig);
            p11 = *(const float2*)(ArB + k0 + 2 * tig + 8);
        }
        uint32_t ah0 = pack_bf(p00.x, p00.y), ah1 = pack_bf(p10.x, p10.y);
        uint32_t ah2 = pack_bf(p01.x, p01.y), ah3 = pack_bf(p11.x, p11.y);
        __nv_bfloat162 h00 = *(__nv_bfloat162*)&ah0, h10 = *(__nv_bfloat162*)&ah1;
        __nv_bfloat162 h01 = *(__nv_bfloat162*)&ah2, h11 = *(__nv_bfloat162*)&ah3;
        uint32_t al0 = pack_bf(p00.x - __bfloat162float(h00.x), p00.y - __bfloat162float(h00.y));
        uint32_t al1 = pack_bf(p10.x - __bfloat162float(h10.x), p10.y - __bfloat162float(h10.y));
        uint32_t al2 = pack_bf(p01.x - __bfloat162float(h01.x), p01.y - __bfloat162float(h01.y));
        uint32_t al3 = pack_bf(p11.x - __bfloat162float(h11.x), p11.y - __bfloat162float(h11.y));

        const unsigned char* bh = sm + (size_t)g * WROW + (k0 + 2 * tig) * 2;
#pragma unroll
        for (int nt = 0; nt < 16; nt++) {
            uint32_t bh0 = *(const uint32_t*)(bh + nt * 8 * WROW);
            uint32_t bh1 = *(const uint32_t*)(bh + nt * 8 * WROW + 16);
            mma_bf16(acc[nt], ah0, ah1, ah2, ah3, bh0, bh1);
            mma_bf16(acc[nt], al0, al1, al2, al3, bh0, bh1);
            uint32_t bl0 = *(const uint32_t*)(bh + WLO + nt * 8 * WROW);
            uint32_t bl1 = *(const uint32_t*)(bh + WLO + nt * 8 * WROW + 16);
            mma_bf16(acc[nt], ah0, ah1, ah2, ah3, bl0, bl1);
        }
    }
}

// Second GEMM with A operand coming from register accumulators.
__device__ __forceinline__ void gemm_core_reg(
    const float4 a1[16], const unsigned char* sm, int lane, float4 acc[16])
{
    const int g = lane >> 2, tig = lane & 3;
#pragma unroll
    for (int kt = 0; kt < 8; kt++) {
        float x0 = a1[2*kt].x,   y0 = a1[2*kt].y;
        float x1 = a1[2*kt].z,   y1 = a1[2*kt].w;
        float x2 = a1[2*kt+1].x, y2 = a1[2*kt+1].y;
        float x3 = a1[2*kt+1].z, y3 = a1[2*kt+1].w;
        uint32_t ah0 = pack_bf(x0, y0), ah1 = pack_bf(x1, y1);
        uint32_t ah2 = pack_bf(x2, y2), ah3 = pack_bf(x3, y3);
        __nv_bfloat162 h0 = *(__nv_bfloat162*)&ah0, h1 = *(__nv_bfloat162*)&ah1;
        __nv_bfloat162 h2 = *(__nv_bfloat162*)&ah2, h3 = *(__nv_bfloat162*)&ah3;
        uint32_t al0 = pack_bf(x0 - __bfloat162float(h0.x), y0 - __bfloat162float(h0.y));
        uint32_t al1 = pack_bf(x1 - __bfloat162float(h1.x), y1 - __bfloat162float(h1.y));
        uint32_t al2 = pack_bf(x2 - __bfloat162float(h2.x), y2 - __bfloat162float(h2.y));
        uint32_t al3 = pack_bf(x3 - __bfloat162float(h3.x), y3 - __bfloat162float(h3.y));

        const unsigned char* bh = sm + (size_t)g * WROW + (kt * 16 + 2 * tig) * 2;
#pragma unroll
        for (int nt = 0; nt < 16; nt++) {
            uint32_t bh0 = *(const uint32_t*)(bh + nt * 8 * WROW);
            uint32_t bh1 = *(const uint32_t*)(bh + nt * 8 * WROW + 16);
            mma_bf16(acc[nt], ah0, ah1, ah2, ah3, bh0, bh1);
            mma_bf16(acc[nt], al0, al1, al2, al3, bh0, bh1);
            uint32_t bl0 = *(const uint32_t*)(bh + WLO + nt * 8 * WROW);
            uint32_t bl1 = *(const uint32_t*)(bh + WLO + nt * 8 * WROW + 16);
            mma_bf16(acc[nt], ah0, ah1, ah2, ah3, bl0, bl1);
        }
    }
}

// ---------------- prep: zero counters + weight images in ONE launch ----------------
#define ZB 1094   // cdiv(2*NSEG_TOT,256)
__global__ void prep_k(const float* __restrict__ W0, const float* __restrict__ W1,
                       const float* __restrict__ W2, const float* __restrict__ W3,
                       const float* __restrict__ W4, const float* __restrict__ W5,
                       const float* __restrict__ W6, const float* __restrict__ W7,
                       unsigned char* __restrict__ imgbase) {
    if (blockIdx.x < ZB) {
        int i = blockIdx.x * 256 + threadIdx.x;
        if (i < 2 * NSEG_TOT) g_dc[i] = 0;
        return;
    }
    int bb = blockIdx.x - ZB;
    int b = bb >> 6;
    const float* W;
    if      (b == 0) W = W0; else if (b == 1) W = W1;
    else if (b == 2) W = W2; else if (b == 3) W = W3;
    else if (b == 4) W = W4; else if (b == 5) W = W5;
    else if (b == 6) W = W6; else              W = W7;
    unsigned char* img = imgbase + (size_t)b * WIMGSZ;
    int i = (bb & 63) * 256 + threadIdx.x;
    int n = i >> 7, k = i & 127;
    float w = W[k * 128 + n];
    __nv_bfloat16 h = __float2bfloat16(w);
    __nv_bfloat16 l = __float2bfloat16(w - __bfloat162float(h));
    *(uint16_t*)(img + n * WROW + k * 2) = __bfloat16_as_ushort(h);
    *(uint16_t*)(img + WLO + n * WROW + k * 2) = __bfloat16_as_ushort(l);
}

// ---------------- CSR build ----------------
__global__ void hist3(const int* __restrict__ d1, const int* __restrict__ d2,
                      const int* __restrict__ d3, int E1, int E2, int E3) {
    int i = blockIdx.x * 256 + threadIdx.x;
    if (i < E1) atomicAdd(g_dc + d1[i], 1);
    else if (i < E1 + E2) atomicAdd(g_dc + SEG_GS + d2[i - E1], 1);
    else if (i < E1 + E2 + E3) atomicAdd(g_dc + SEG_GG + d3[i - E1 - E2], 1);
}
__device__ __forceinline__ void seg_map(int b, int& degoff, int& nd, int& boff, int& lb) {
    if (b < NB_SG)            { degoff = 0;      nd = N_GENE; boff = 0;             lb = b; }
    else if (b < NB_SG+NB_GS) { degoff = SEG_GS; nd = N_SNP;  boff = NB_SG;         lb = b - NB_SG; }
    else                      { degoff = SEG_GG; nd = N_GENE; boff = NB_SG + NB_GS; lb = b - NB_SG - NB_GS; }
}
__global__ void bsum3() {
    __shared__ int sw[32];
    int degoff, nd, boff, lb;
    seg_map(blockIdx.x, degoff, nd, boff, lb);
    int i = lb * 1024 + threadIdx.x;
    int v = (i < nd) ? g_dc[degoff + i] : 0;
#pragma unroll
    for (int o = 16; o; o >>= 1) v += __shfl_xor_sync(0xffffffffu, v, o);
    if ((threadIdx.x & 31) == 0) sw[threadIdx.x >> 5] = v;
    __syncthreads();
    if (threadIdx.x < 32) {
        int t = sw[threadIdx.x];
#pragma unroll
        for (int o = 16; o; o >>= 1) t += __shfl_xor_sync(0xffffffffu, t, o);
        if (threadIdx.x == 0) g_bsum[boff + lb] = t;
    }
}
__global__ void scan3() {
    __shared__ int sm[1024];
    __shared__ int sbase;
    int degoff, nd, boff, lb;
    seg_map(blockIdx.x, degoff, nd, boff, lb);
    int* rp = (blockIdx.x < NB_SG) ? g_rp_sg
            : (blockIdx.x < NB_SG + NB_GS) ? g_rp_gs : g_rp_gg;
    int tid = threadIdx.x;
    if (tid == 0) sbase = 0;
    __syncthreads();
    if (tid < lb) atomicAdd(&sbase, g_bsum[boff + tid]);
    int i = lb * 1024 + tid;
    int v = (i < nd) ? g_dc[degoff + i] : 0;
    sm[tid] = v;
    __syncthreads();
#pragma unroll
    for (int off = 1; off < 1024; off <<= 1) {
        int t = (tid >= off) ? sm[tid - off] : 0;
        __syncthreads();
        sm[tid] += t;
        __syncthreads();
    }
    int incl = sm[tid];
    int base = sbase;
    if (i < nd) rp[i] = base + incl - v;
    if (i == nd - 1) rp[nd] = base + incl;
}
__global__ void scatter3(const int* __restrict__ s1, const int* __restrict__ d1,
                         const int* __restrict__ s2, const int* __restrict__ d2,
                         const int* __restrict__ s3, const int* __restrict__ d3,
                         int E1, int E2, int E3) {
    int i = blockIdx.x * 256 + threadIdx.x;
    if (i < E1) {
        int d = d1[i];
        g_ss_sg[g_rp_sg[d] + atomicAdd(g_dc + NSEG_TOT + d, 1)] = s1[i];
    } else if (i < E1 + E2) {
        int e = i - E1, d = d2[e];
        g_ss_gs[g_rp_gs[d] + atomicAdd(g_dc + NSEG_TOT + SEG_GS + d, 1)] = s2[e];
    } else if (i < E1 + E2 + E3) {
        int e = i - E1 - E2, d = d3[e];
        g_ss_gg[g_rp_gg[d] + atomicAdd(g_dc + NSEG_TOT + SEG_GG + d, 1)] = s3[e];
    }
}

// ---------------- merged projection GEMM: snp + gene, 2 row-tiles per CTA -----------
#define TG_SMEM1 (WIMGSZ + 16)
#define PROJ_TPB 2

__global__ void __launch_bounds__(256) proj_h(
    const float* __restrict__ As, const float* __restrict__ Ag,
    const unsigned char* __restrict__ imgS, const unsigned char* __restrict__ imgG,
    const float* __restrict__ bS, const float* __restrict__ bG,
    const float* __restrict__ a_src, const float* __restrict__ a_dst,
    int l, int nsblk2)
{
    extern __shared__ unsigned char smem[];
    const int tid = threadIdx.x, wid = tid >> 5, lane = tid & 31;
    const int g = lane >> 2, tig = lane & 3;
    const bool is_snp = blockIdx.x < nsblk2;
    const int blk0 = (is_snp ? blockIdx.x : blockIdx.x - nsblk2) * PROJ_TPB;
    const float* A = is_snp ? As : Ag;
    const unsigned char* Bimg = is_snp ? imgS : imgG;
    const float* bias = is_snp ? bS : bG;
    const int M = is_snp ? N_SNP : N_GENE;
    __half* Ch = is_snp ? g_hsh : g_hgh;

    {
        const uint4* src = (const uint4*)Bimg;
        uint4* dst = (uint4*)smem;
#pragma unroll
        for (int i = 0; i < 17; i++) {
            int idx = tid + 256 * i;
            if (idx < WIMGSZ / 16) dst[idx] = src[idx];
        }
    }
    __syncthreads();

    const float* vv[4];
    float* sb[4];
    int nv;
    if (is_snp) {
        nv = 2;
        vv[0] = a_src + (l * 3 + 0) * 128; sb[0] = g_ssrc_sg;
        vv[1] = a_dst + (l * 3 + 1) * 128; sb[1] = g_sdst_gs;
        vv[2] = nullptr; vv[3] = nullptr;
    } else {
        nv = 4;
        vv[0] = a_dst + (l * 3 + 0) * 128; sb[0] = g_sdst_sg;
        vv[1] = a_src + (l * 3 + 1) * 128; sb[1] = g_ssrc_gs;
        vv[2] = a_src + (l * 3 + 2) * 128; sb[2] = g_ssrc_gg;
        vv[3] = a_dst + (l * 3 + 2) * 128; sb[3] = g_sdst_gg;
    }

    for (int t = 0; t < PROJ_TPB; t++) {
        const int blk = blk0 + t;
        const int rowA = blk * 128 + wid * 16 + g;
        const int rowB = rowA + 8;
        const bool vA = rowA < M, vB = rowB < M;
        if (!vA && !vB) break;

        float4 acc[16];
#pragma unroll
        for (int nt = 0; nt < 16; nt++) acc[nt] = make_float4(0.f, 0.f, 0.f, 0.f);
        gemm_core(A, rowA, rowB, vA, vB, smem, lane, acc);

#pragma unroll
        for (int nt = 0; nt < 16; nt++) {
            int col = nt * 8 + 2 * tig;
            float b0 = bias[col], b1 = bias[col + 1];
            acc[nt].x += b0; acc[nt].y += b1;
            acc[nt].z += b0; acc[nt].w += b1;
        }

#pragma unroll
        for (int nt = 0; nt < 16; nt++) {
            int col = nt * 8 + 2 * tig;
            if (vA) *((__half2*)(Ch + (size_t)rowA * 128 + col)) = __floats2half2_rn(acc[nt].x, acc[nt].y);
            if (vB) *((__half2*)(Ch + (size_t)rowB * 128 + col)) = __floats2half2_rn(acc[nt].z, acc[nt].w);
        }

#pragma unroll
        for (int v = 0; v < 4; v++) {
            if (v < nv) {
#pragma unroll
                for (int hd = 0; hd < 8; hd++) {
                    float a0 = __ldg(vv[v] + 16 * hd + 2 * tig);
                    float a1 = __ldg(vv[v] + 16 * hd + 2 * tig + 1);
                    float a2 = __ldg(vv[v] + 16 * hd + 8 + 2 * tig);
                    float a3 = __ldg(vv[v] + 16 * hd + 8 + 2 * tig + 1);
                    float pA = acc[2*hd].x * a0 + acc[2*hd].y * a1
                             + acc[2*hd+1].x * a2 + acc[2*hd+1].y * a3;
                    float pB = acc[2*hd].z * a0 + acc[2*hd].w * a1
                             + acc[2*hd+1].z * a2 + acc[2*hd+1].w * a3;
                    pA += __shfl_xor_sync(0xffffffffu, pA, 1);
                    pA += __shfl_xor_sync(0xffffffffu, pA, 2);
                    pB += __shfl_xor_sync(0xffffffffu, pB, 1);
                    pB += __shfl_xor_sync(0xffffffffu, pB, 2);
                    if (tig == 0) {
                        if (vA) sb[v][rowA * 8 + hd] = pA;
                        if (vB) sb[v][rowB * 8 + hd] = pB;
                    }
                }
            }
        }
    }
}

// ---------------- semantic GEMM: tanh colsums accumulated atomically into g_sem ----
#define TG_SMEM_SEM (WIMGSZ + 512)

__global__ void __launch_bounds__(256) tgemm_sem(
    const unsigned char* __restrict__ Bimg, const float* __restrict__ bias, int nhalf)
{
    extern __shared__ unsigned char smem[];
    float* scs = (float*)(smem + WIMGSZ);
    const int tid = threadIdx.x, wid = tid >> 5, lane = tid & 31;
    const int g = lane >> 2, tig = lane & 3;
    int blk = blockIdx.x;
    const float* A = g_o_sg;
    int msel = 0;
    if (blk >= nhalf) { A = g_o_gg; blk -= nhalf; msel = 1; }

    {
        const uint4* src = (const uint4*)Bimg;
        uint4* dst = (uint4*)smem;
#pragma unroll
        for (int i = 0; i < 17; i++) {
            int idx = tid + 256 * i;
            if (idx < WIMGSZ / 16) dst[idx] = src[idx];
        }
    }
    if (tid < 128) scs[tid] = 0.f;
    __syncthreads();

    const int rowA = blk * 128 + wid * 16 + g;
    const int rowB = rowA + 8;
    const bool vA = rowA < N_GENE, vB = rowB < N_GENE;

    float4 acc[16];
#pragma unroll
    for (int nt = 0; nt < 16; nt++) acc[nt] = make_float4(0.f, 0.f, 0.f, 0.f);
    gemm_core(A, rowA, rowB, vA, vB, smem, lane, acc);

#pragma unroll
    for (int nt = 0; nt < 16; nt++) {
        int col = nt * 8 + 2 * tig;
        float b0 = bias[col], b1 = bias[col + 1];
        float s0 = 0.f, s1 = 0.f;
        if (vA) { s0 += tanhf(acc[nt].x + b0); s1 += tanhf(acc[nt].y + b1); }
        if (vB) { s0 += tanhf(acc[nt].z + b0); s1 += tanhf(acc[nt].w + b1); }
        atomicAdd(scs + col, s0);
        atomicAdd(scs + col + 1, s1);
    }
    __syncthreads();
    if (tid < 128) atomicAdd(g_sem + msel * 128 + tid, scs[tid]);
}

// ---------------- final fused MLP (4 row-tiles per CTA) ----------------
#define TG_SMEM_FIN (2 * WIMGSZ)
#define FIN_TPB 4

__global__ void __launch_bounds__(256) final2(
    const float* __restrict__ A,
    const unsigned char* __restrict__ img1, const unsigned char* __restrict__ img2,
    const float* __restrict__ b1, const float* __restrict__ b2v,
    const float* __restrict__ W2, const float* __restrict__ b2,
    float* __restrict__ outp, int M)
{
    extern __shared__ unsigned char smem[];
    const int tid = threadIdx.x, wid = tid >> 5, lane = tid & 31;
    const int g = lane >> 2, tig = lane & 3;

    {
        const uint4* s1 = (const uint4*)img1;
        const uint4* s2 = (const uint4*)img2;
        uint4* d1 = (uint4*)smem;
        uint4* d2 = (uint4*)(smem + WIMGSZ);
#pragma unroll
        for (int i = 0; i < 17; i++) {
            int idx = tid + 256 * i;
            if (idx < WIMGSZ / 16) { d1[idx] = s1[idx]; d2[idx] = s2[idx]; }
        }
    }
    __syncthreads();

    for (int t = 0; t < FIN_TPB; t++) {
        const int rowA = (blockIdx.x * FIN_TPB + t) * 128 + wid * 16 + g;
        const int rowB = rowA + 8;
        const bool vA = rowA < M, vB = rowB < M;
        if (!vA && !vB) break;

        float4 acc[16];
#pragma unroll
        for (int nt = 0; nt < 16; nt++) acc[nt] = make_float4(0.f, 0.f, 0.f, 0.f);
        gemm_core(A, rowA, rowB, vA, vB, smem, lane, acc);

#pragma unroll
        for (int nt = 0; nt < 16; nt++) {
            int col = nt * 8 + 2 * tig;
            float c0 = b1[col], c1 = b1[col + 1];
            acc[nt].x = fmaxf(acc[nt].x + c0, 0.f);
            acc[nt].y = fmaxf(acc[nt].y + c1, 0.f);
            acc[nt].z = fmaxf(acc[nt].z + c0, 0.f);
            acc[nt].w = fmaxf(acc[nt].w + c1, 0.f);
        }

        float4 acc2[16];
#pragma unroll
        for (int nt = 0; nt < 16; nt++) acc2[nt] = make_float4(0.f, 0.f, 0.f, 0.f);
        gemm_core_reg(acc, smem + WIMGSZ, lane, acc2);

        float pA0 = 0.f, pA1 = 0.f, pB0 = 0.f, pB1 = 0.f;
#pragma unroll
        for (int nt = 0; nt < 16; nt++) {
            int col = nt * 8 + 2 * tig;
            float c0 = b2v[col], c1 = b2v[col + 1];
            float rx = fmaxf(acc2[nt].x + c0, 0.f), ry = fmaxf(acc2[nt].y + c1, 0.f);
            float rz = fmaxf(acc2[nt].z + c0, 0.f), rw = fmaxf(acc2[nt].w + c1, 0.f);
            float w00 = __ldg(W2 + col * 2), w01 = __ldg(W2 + col * 2 + 1);
            float w10 = __ldg(W2 + (col + 1) * 2), w11 = __ldg(W2 + (col + 1) * 2 + 1);
            pA0 += rx * w00 + ry * w10; pA1 += rx * w01 + ry * w11;
            pB0 += rz * w00 + rw * w10; pB1 += rz * w01 + rw * w11;
        }
        pA0 += __shfl_xor_sync(0xffffffffu, pA0, 1); pA0 += __shfl_xor_sync(0xffffffffu, pA0, 2);
        pA1 += __shfl_xor_sync(0xffffffffu, pA1, 1); pA1 += __shfl_xor_sync(0xffffffffu, pA1, 2);
        pB0 += __shfl_xor_sync(0xffffffffu, pB0, 1); pB0 += __shfl_xor_sync(0xffffffffu, pB0, 2);
        pB1 += __shfl_xor_sync(0xffffffffu, pB1, 1); pB1 += __shfl_xor_sync(0xffffffffu, pB1, 2);
        if (tig == 0) {
            if (vA) { outp[(size_t)rowA * 2] = pA0 + b2[0]; outp[(size_t)rowA * 2 + 1] = pA1 + b2[1]; }
            if (vB) { outp[(size_t)rowB * 2] = pB0 + b2[0]; outp[(size_t)rowB * 2 + 1] = pB1 + b2[1]; }
        }
    }
}

// ---------------- CSR aggregation: HALF-WARP per destination, fused snp LN ----------
// All reductions are 16-lane. Block 0 zeroes g_sem for tgemm_sem.
__global__ void __launch_bounds__(256) agg3(
    const float* __restrict__ ln_gp, const float* __restrict__ ln_bp,
    const float* __restrict__ fw, int layer1)
{
    if (blockIdx.x == 0) g_sem[threadIdx.x] = 0.f;

    int w = blockIdx.x * 16 + (threadIdx.x >> 4);   // half-warp = one destination
    const __half* hsrc;
    const float *ssrc, *sdst;
    const int *rp, *ss;
    float* out;
    const float* prev = nullptr;
    int d;
    bool fuse = false;
    if (w < N_GENE) {
        d = w; hsrc = g_hsh; ssrc = g_ssrc_sg; sdst = g_sdst_sg;
        rp = g_rp_sg; ss = g_ss_sg; out = g_o_sg;
    } else if (w < N_GENE + N_SNP) {
        d = w - N_GENE; hsrc = g_hgh; ssrc = g_ssrc_gs; sdst = g_sdst_gs;
        rp = g_rp_gs; ss = g_ss_gs;
        fuse = true;
        prev = layer1 ? g_out_s0 : nullptr;
        out = layer1 ? g_buf1 : g_out_s0;
    } else if (w < 2 * N_GENE + N_SNP) {
        d = w - (N_GENE + N_SNP); hsrc = g_hgh; ssrc = g_ssrc_gg; sdst = g_sdst_gg;
        rp = g_rp_gg; ss = g_ss_gg; out = g_o_gg;
    } else return;

    const int l16 = threadIdx.x & 15, hd = l16 >> 1;
    float sdh = __ldg(sdst + d * 8 + hd);
    int beg = __ldg(rp + d), end = __ldg(rp + d + 1);

    float acc[8];
#pragma unroll
    for (int j = 0; j < 8; j++) acc[j] = 0.f;
    float se = 0.f;

#pragma unroll 2
    for (int i = beg; i < end; i++) {
        int s = __ldg(ss + i);
        float a = __ldg(ssrc + s * 8 + hd) + sdh;
        uint4 u = *((const uint4*)(hsrc + (size_t)s * 128) + l16);
        a = a > 0.f ? a : NEG * a;
        float e = __expf(a);
        float2 f0 = __half22float2(*(__half2*)&u.x);
        float2 f1 = __half22float2(*(__half2*)&u.y);
        float2 f2 = __half22float2(*(__half2*)&u.z);
        float2 f3 = __half22float2(*(__half2*)&u.w);
        acc[0] = fmaf(e, f0.x, acc[0]); acc[1] = fmaf(e, f0.y, acc[1]);
        acc[2] = fmaf(e, f1.x, acc[2]); acc[3] = fmaf(e, f1.y, acc[3]);
        acc[4] = fmaf(e, f2.x, acc[4]); acc[5] = fmaf(e, f2.y, acc[5]);
        acc[6] = fmaf(e, f3.x, acc[6]); acc[7] = fmaf(e, f3.y, acc[7]);
        se += e;
    }
    // 16-lane sum of se (edges were distributed... here all lanes saw the same
    // edges; se identical across lanes -> no reduction needed for se)
    float inv = 1.f / (se + 1e-16f);
    float r[8];
#pragma unroll
    for (int j = 0; j < 8; j++) r[j] = fmaxf(acc[j] * inv, 0.f);

    if (!fuse) {
        float4* op = (float4*)(out + (size_t)d * 128 + l16 * 8);
        op[0] = make_float4(r[0], r[1], r[2], r[3]);
        op[1] = make_float4(r[4], r[5], r[6], r[7]);
        return;
    }

    // fused LayerNorm (+ layer fusion) for the snp path; 16-lane reductions
    float ps = r[0] + r[1] + r[2] + r[3] + r[4] + r[5] + r[6] + r[7];
#pragma unroll
    for (int o = 8; o; o >>= 1) ps += __shfl_xor_sync(0xffffffffu, ps, o);
    float mu = ps * (1.f / 128.f);
    float pv = 0.f;
#pragma unroll
    for (int j = 0; j < 8; j++) { float dl = r[j] - mu; pv += dl * dl; }
#pragma unroll
    for (int o = 8; o; o >>= 1) pv += __shfl_xor_sync(0xffffffffu, pv, o);
    float rs = rsqrtf(pv * (1.f / 128.f) + 1e-5f);
    {
        float4 g0 = __ldg((const float4*)ln_gp + l16 * 2);
        float4 g1 = __ldg((const float4*)ln_gp + l16 * 2 + 1);
        float4 b0 = __ldg((const float4*)ln_bp + l16 * 2);
        float4 b1 = __ldg((const float4*)ln_bp + l16 * 2 + 1);
        float4 o0, o1;
        o0.x = (r[0] - mu) * rs * g0.x + b0.x;
        o0.y = (r[1] - mu) * rs * g0.y + b0.y;
        o0.z = (r[2] - mu) * rs * g0.z + b0.z;
        o0.w = (r[3] - mu) * rs * g0.w + b0.w;
        o1.x = (r[4] - mu) * rs * g1.x + b1.x;
        o1.y = (r[5] - mu) * rs * g1.y + b1.y;
        o1.z = (r[6] - mu) * rs * g1.z + b1.z;
        o1.w = (r[7] - mu) * rs * g1.w + b1.w;
        if (prev) {
            float w0 = fw[0], w1 = fw[1];
            float iw = 1.f / (w0 + w1);
            float4 p0 = *((const float4*)(prev + (size_t)d * 128 + l16 * 8));
            float4 p1 = *((const float4*)(prev + (size_t)d * 128 + l16 * 8) + 1);
            o0.x = (w0 * p0.x + w1 * o0.x) * iw;
            o0.y = (w0 * p0.y + w1 * o0.y) * iw;
            o0.z = (w0 * p0.z + w1 * o0.z) * iw;
            o0.w = (w0 * p0.w + w1 * o0.w) * iw;
            o1.x = (w0 * p1.x + w1 * o1.x) * iw;
            o1.y = (w0 * p1.y + w1 * o1.y) * iw;
            o1.z = (w0 * p1.z + w1 * o1.z) * iw;
            o1.w = (w0 * p1.w + w1 * o1.w) * iw;
        }
        float4* op = (float4*)(out + (size_t)d * 128 + l16 * 8);
        op[0] = o0; op[1] = o1;
    }
}

// ---------------- gene combine + inline cheap semantic softmax + LayerNorm ----------
__global__ void __launch_bounds__(256) combine_all(
    const float* __restrict__ q,
    const float* __restrict__ ln_gp, const float* __restrict__ ln_bp,
    const float* __restrict__ fw, int layer1)
{
    __shared__ float sw[8];
    __shared__ float sattn[2];
    const int tid = threadIdx.x, wid = tid >> 5, lane = tid & 31;

    {
        int col = tid & 127;
        float v = __ldg(q + col) * (g_sem[tid] / 20000.f);
#pragma unroll
        for (int o = 16; o; o >>= 1) v += __shfl_xor_sync(0xffffffffu, v, o);
        if (lane == 0) sw[wid] = v;
        __syncthreads();
        if (tid == 0) {
            float s0 = sw[0] + sw[1] + sw[2] + sw[3];
            float s1 = sw[4] + sw[5] + sw[6] + sw[7];
            float mx = fmaxf(s0, s1);
            float e0 = __expf(s0 - mx), e1 = __expf(s1 - mx);
            float iv = 1.f / (e0 + e1);
            sattn[0] = e0 * iv; sattn[1] = e1 * iv;
        }
        __syncthreads();
    }
    const float a0 = sattn[0], a1 = sattn[1];

    int n = (blockIdx.x * 256 + tid) >> 5;
    if (n >= N_GENE) return;
    const float* prev = layer1 ? g_out_g0 : nullptr;
    float* out = layer1 ? (g_buf1 + (size_t)N_SNP * 128) : g_out_g0;
    float4 v = *((const float4*)(g_o_sg + (size_t)n * 128) + lane);
    {
        float4 u = *((const float4*)(g_o_gg + (size_t)n * 128) + lane);
        v.x = a0 * v.x + a1 * u.x;
        v.y = a0 * v.y + a1 * u.y;
        v.z = a0 * v.z + a1 * u.z;
        v.w = a0 * v.w + a1 * u.w;
    }
    float s = v.x + v.y + v.z + v.w;
#pragma unroll
    for (int o = 16; o; o >>= 1) s += __shfl_xor_sync(0xffffffffu, s, o);
    float mu = s * (1.f / 128.f);
    float dx = v.x - mu, dy = v.y - mu, dz = v.z - mu, dw = v.w - mu;
    float qv = dx * dx + dy * dy + dz * dz + dw * dw;
#pragma unroll
    for (int o = 16; o; o >>= 1) qv += __shfl_xor_sync(0xffffffffu, qv, o);
    float rs = rsqrtf(qv * (1.f / 128.f) + 1e-5f);
    float4 g4 = *((const float4*)ln_gp + lane);
    float4 b4 = *((const float4*)ln_bp + lane);
    float4 r;
    r.x = dx * rs * g4.x + b4.x;
    r.y = dy * rs * g4.y + b4.y;
    r.z = dz * rs * g4.z + b4.z;
    r.w = dw * rs * g4.w + b4.w;
    if (prev) {
        float w0 = fw[0], w1 = fw[1];
        float inv = 1.f / (w0 + w1);
        float4 p = *((const float4*)(prev + (size_t)n * 128) + lane);
        r.x = (w0 * p.x + w1 * r.x) * inv;
        r.y = (w0 * p.y + w1 * r.y) * inv;
        r.z = (w0 * p.z + w1 * r.z) * inv;
        r.w = (w0 * p.w + w1 * r.w) * inv;
    }
    *((float4*)(out + (size_t)n * 128) + lane) = r;
}

static inline int cdiv(long a, int b) { return (int)((a + b - 1) / b); }

extern "C" void kernel_launch(void* const* d_in, const int* in_sizes, int n_in,
                              void* d_out, int out_size)
{
    const float* x_snp  = (const float*)d_in[0];
    const float* x_gene = (const float*)d_in[1];
    const float* Wp_snp = (const float*)d_in[2];
    const float* bp_snp = (const float*)d_in[3];
    const float* Wp_gene= (const float*)d_in[4];
    const float* bp_gene= (const float*)d_in[5];
    const float* a_src  = (const float*)d_in[6];
    const float* a_dst  = (const float*)d_in[7];
    const float* Wk     = (const float*)d_in[8];
    const float* bk     = (const float*)d_in[9];
    const float* qvp    = (const float*)d_in[10];
    const float* ln_g   = (const float*)d_in[11];
    const float* ln_b   = (const float*)d_in[12];
    const float* fw     = (const float*)d_in[13];
    const float* Wfp    = (const float*)d_in[14];
    const float* bfp    = (const float*)d_in[15];
    const float* Wo1    = (const float*)d_in[16];
    const float* bo1    = (const float*)d_in[17];
    const float* Wo2    = (const float*)d_in[18];
    const float* bo2    = (const float*)d_in[19];
    const int* sg_s = (const int*)d_in[20];
    const int* sg_d = (const int*)d_in[21];
    const int* gs_s = (const int*)d_in[22];
    const int* gs_d = (const int*)d_in[23];
    const int* gg_s = (const int*)d_in[24];
    const int* gg_d = (const int*)d_in[25];
    const int E_sg = in_sizes[20], E_gs = in_sizes[22], E_gg = in_sizes[24];

    float *out_s0, *out_g0, *buf1;
    unsigned char* wimg;
    cudaGetSymbolAddress((void**)&out_s0, g_out_s0);
    cudaGetSymbolAddress((void**)&out_g0, g_out_g0);
    cudaGetSymbolAddress((void**)&buf1, g_buf1);
    cudaGetSymbolAddress((void**)&wimg, g_wimg);

    cudaFuncSetAttribute(proj_h, cudaFuncAttributeMaxDynamicSharedMemorySize, TG_SMEM1);
    cudaFuncSetAttribute(tgemm_sem, cudaFuncAttributeMaxDynamicSharedMemorySize, TG_SMEM_SEM);
    cudaFuncSetAttribute(final2, cudaFuncAttributeMaxDynamicSharedMemorySize, TG_SMEM_FIN);

    prep_k<<<ZB + 512, 256>>>(Wp_snp, Wp_snp + 16384, Wp_gene, Wp_gene + 16384,
                              Wk, Wk + 16384, Wfp, Wo1, wimg);

    const int E_tot = E_sg + E_gs + E_gg;
    hist3<<<cdiv(E_tot, 256), 256>>>(sg_d, gs_d, gg_d, E_sg, E_gs, E_gg);
    bsum3<<<NB_TOT, 1024>>>();
    scan3<<<NB_TOT, 1024>>>();
    scatter3<<<cdiv(E_tot, 256), 256>>>(sg_s, sg_d, gs_s, gs_d, gg_s, gg_d,
                                        E_sg, E_gs, E_gg);

    const int TS = cdiv(N_SNP, 128), TG = cdiv(N_GENE, 128), TA = cdiv(N_ALL, 128);
    const int TS2 = cdiv(TS, PROJ_TPB), TG2 = cdiv(TG, PROJ_TPB);

    for (int l = 0; l < 2; ++l) {
        const float* ins = l ? out_s0 : x_snp;
        const float* ing = l ? out_g0 : x_gene;

        proj_h<<<TS2 + TG2, 256, TG_SMEM1>>>(ins, ing,
            wimg + l * WIMGSZ, wimg + (2 + l) * WIMGSZ,
            bp_snp + l * 128, bp_gene + l * 128, a_src, a_dst, l, TS2);

        agg3<<<cdiv(2 * N_GENE + N_SNP, 16), 256>>>(ln_g + l * 128, ln_b + l * 128, fw, l);

        tgemm_sem<<<2 * TG, 256, TG_SMEM_SEM>>>(wimg + (4 + l) * WIMGSZ, bk + l * 128, TG);

        combine_all<<<cdiv((long)N_GENE * 32, 256), 256>>>(qvp + l * 128,
            ln_g + l * 128, ln_b + l * 128, fw, l);
    }

    final2<<<cdiv(TA, FIN_TPB), 256, TG_SMEM_FIN>>>(buf1, wimg + 6 * WIMGSZ, wimg + 7 * WIMGSZ,
                                                    bfp, bo1, Wo2, bo2, (float*)d_out, N_ALL);
}